// round 1
// baseline (speedup 1.0000x reference)
#include <cuda_runtime.h>
#include <math.h>

#define BATCH 32
#define TLEN  512
#define DDIM  512
#define PNUM  200
#define NPS   8
#define MDIM  (BATCH*TLEN)   // 16384
#define NDIM  (PNUM*NPS)     // 1600
#define NEGC  (-100000.0f)

// Scratch (static device globals — allocation-free per harness rules)
__device__ float g_dist[(size_t)MDIM * NDIM];   // ~105 MB
__device__ float g_pT[(size_t)DDIM * NDIM];     // normalized prototypes, [k][n]
__device__ float g_invnx[MDIM];

// ---------------------------------------------------------------------------
// Kernel 1: inverse L2 norm of each x row (m = b*T + t), 128 threads/row
// ---------------------------------------------------------------------------
__global__ void norm_x_kernel(const float* __restrict__ x) {
    int m = blockIdx.x;
    const float4* row = (const float4*)(x + (size_t)m * DDIM);
    float4 v = row[threadIdx.x];
    float s = v.x*v.x + v.y*v.y + v.z*v.z + v.w*v.w;
    #pragma unroll
    for (int o = 16; o; o >>= 1) s += __shfl_down_sync(0xffffffffu, s, o);
    __shared__ float ws[4];
    if ((threadIdx.x & 31) == 0) ws[threadIdx.x >> 5] = s;
    __syncthreads();
    if (threadIdx.x == 0) {
        float t = ws[0] + ws[1] + ws[2] + ws[3];
        g_invnx[m] = 1.0f / fmaxf(sqrtf(t), 1e-12f);
    }
}

// ---------------------------------------------------------------------------
// Kernel 2: normalize prototypes over d and write transposed [k][n] matrix
// proto layout: [p][d][i] ; g_pT[d*N + p*8 + i] = proto[p][d][i] / ||proto[p][:][i]||
// ---------------------------------------------------------------------------
__global__ void proto_prep_kernel(const float* __restrict__ proto) {
    int p = blockIdx.x;
    __shared__ float sp[DDIM * NPS];   // 16 KB
    __shared__ float sinv[NPS];
    const float* base = proto + (size_t)p * DDIM * NPS;
    for (int idx = threadIdx.x; idx < DDIM * NPS; idx += blockDim.x)
        sp[idx] = base[idx];
    __syncthreads();
    int w = threadIdx.x >> 5, lane = threadIdx.x & 31;
    if (w < NPS) {
        float s = 0.0f;
        for (int d = lane; d < DDIM; d += 32) { float v = sp[d*NPS + w]; s += v * v; }
        #pragma unroll
        for (int o = 16; o; o >>= 1) s += __shfl_down_sync(0xffffffffu, s, o);
        if (lane == 0) sinv[w] = 1.0f / fmaxf(sqrtf(s), 1e-12f);
    }
    __syncthreads();
    for (int idx = threadIdx.x; idx < DDIM * NPS; idx += blockDim.x) {
        int d = idx >> 3, i = idx & 7;
        g_pT[(size_t)d * NDIM + p * NPS + i] = sp[idx] * sinv[i];
    }
}

// ---------------------------------------------------------------------------
// Kernel 3: fp32 GEMM  dist[m][n] = (x[m,:] . pT[:,n]) * invnx[m], + timeline mask
// Tiles: 128x64x16, 256 threads, 8x4 per thread
// ---------------------------------------------------------------------------
#define BM 128
#define BN 64
#define BK 16

__global__ void __launch_bounds__(256)
gemm_kernel(const float* __restrict__ X, const float* __restrict__ tmask) {
    __shared__ float As[BK][BM + 1];   // +1 pad: conflict-free transpose stores
    __shared__ float Bs[BK][BN];
    int bm = blockIdx.y * BM, bn = blockIdx.x * BN;
    int tid = (int)threadIdx.x;
    int r = tid >> 4;        // 0..15 -> 8 rows each
    int c = tid & 15;        // 0..15 -> 4 cols each

    float acc[8][4];
    #pragma unroll
    for (int i = 0; i < 8; i++)
        #pragma unroll
        for (int j = 0; j < 4; j++) acc[i][j] = 0.0f;

    for (int k0 = 0; k0 < DDIM; k0 += BK) {
        #pragma unroll
        for (int q = 0; q < 2; q++) {
            int idx = tid + q * 256;
            int row = idx >> 2, kq = (idx & 3) << 2;
            float4 v = *(const float4*)(X + (size_t)(bm + row) * DDIM + k0 + kq);
            As[kq + 0][row] = v.x; As[kq + 1][row] = v.y;
            As[kq + 2][row] = v.z; As[kq + 3][row] = v.w;
        }
        {
            int kk = tid >> 4, nq = (tid & 15) << 2;
            *(float4*)&Bs[kk][nq] = *(const float4*)(g_pT + (size_t)(k0 + kk) * NDIM + bn + nq);
        }
        __syncthreads();
        #pragma unroll
        for (int kk = 0; kk < BK; kk++) {
            float a[8], bb[4];
            #pragma unroll
            for (int i = 0; i < 8; i++) a[i] = As[kk][r * 8 + i];
            #pragma unroll
            for (int j = 0; j < 4; j++) bb[j] = Bs[kk][c * 4 + j];
            #pragma unroll
            for (int i = 0; i < 8; i++)
                #pragma unroll
                for (int j = 0; j < 4; j++)
                    acc[i][j] += a[i] * bb[j];
        }
        __syncthreads();
    }

    #pragma unroll
    for (int i = 0; i < 8; i++) {
        int gm = bm + r * 8 + i;
        float sx = g_invnx[gm];
        float tm = tmask[gm];
        float4 o;
        float* po = (float*)&o;
        #pragma unroll
        for (int j = 0; j < 4; j++) {
            float v = acc[i][j] * sx;
            po[j] = v * tm + (1.0f - tm) * NEGC;
        }
        *(float4*)(g_dist + (size_t)gm * NDIM + bn + c * 4) = o;
    }
}

// ---------------------------------------------------------------------------
// Kernel 4: greedy iterative selection per (b,p) pair, one CTA (256 thr) each.
// Replicates jnp argmax tie-breaks: per-i first-t max, then first-i across i
// (comparator: greater value wins; on exact tie smaller key = i*512+t wins).
// ---------------------------------------------------------------------------
__global__ void __launch_bounds__(256)
select_kernel(const float* __restrict__ ps, float* __restrict__ out) {
    int bp = blockIdx.x;            // b*P + p
    int b = bp / PNUM, p = bp % PNUM;
    __shared__ float ds[TLEN * NPS];            // 16 KB dist tile [t][i]
    __shared__ unsigned char mact[TLEN];
    __shared__ unsigned char msub[NPS];
    __shared__ float wv[8];
    __shared__ int   wk[8];
    __shared__ int   s_pe;
    __shared__ float rec_v[NPS];
    __shared__ int   rec_e[NPS];
    __shared__ int   rec_s[NPS];
    int tid = (int)threadIdx.x;

    const float* gd = g_dist + (size_t)b * TLEN * NDIM + (size_t)p * NPS;
    for (int idx = tid; idx < TLEN * NPS / 4; idx += 256) {
        int t = idx >> 1, h = (idx & 1) << 2;
        *(float4*)&ds[t * NPS + h] = *(const float4*)(gd + (size_t)t * NDIM + h);
    }
    for (int t = tid; t < TLEN; t += 256) mact[t] = 1;
    if (tid < NPS) msub[tid] = 1;
    __syncthreads();

    int pe = 0;
    for (int it = 0; it < NPS; it++) {
        float bv = -INFINITY;
        int   bk = 0x7fffffff;
        #pragma unroll
        for (int q = 0; q < 2; q++) {
            int t = tid + q * 256;
            bool adj;
            if (it == 0)       adj = true;
            else if (it == 1)  adj = (t - pe <= 3) && (pe - t <= 3);
            else               adj = (t > pe) && (t - pe <= 3);
            bool at = adj && (mact[t] != 0);
            float4 lo = *(float4*)&ds[t * NPS];
            float4 hi = *(float4*)&ds[t * NPS + 4];
            float vv[8] = {lo.x, lo.y, lo.z, lo.w, hi.x, hi.y, hi.z, hi.w};
            #pragma unroll
            for (int i = 0; i < NPS; i++) {
                float v = vv[i] + ((at && msub[i]) ? 0.0f : NEGC);
                int k = (i << 9) | t;
                if (v > bv || (v == bv && k < bk)) { bv = v; bk = k; }
            }
        }
        #pragma unroll
        for (int o = 16; o; o >>= 1) {
            float ov = __shfl_down_sync(0xffffffffu, bv, o);
            int   ok = __shfl_down_sync(0xffffffffu, bk, o);
            if (ov > bv || (ov == bv && ok < bk)) { bv = ov; bk = ok; }
        }
        if ((tid & 31) == 0) { wv[tid >> 5] = bv; wk[tid >> 5] = bk; }
        __syncthreads();
        if (tid == 0) {
            float fv = wv[0]; int fk = wk[0];
            #pragma unroll
            for (int w = 1; w < 8; w++)
                if (wv[w] > fv || (wv[w] == fv && wk[w] < fk)) { fv = wv[w]; fk = wk[w]; }
            int t = fk & (TLEN - 1), i = fk >> 9;
            mact[t] = 0; msub[i] = 0;
            s_pe = t;
            rec_v[it] = fv; rec_e[it] = t; rec_s[it] = i;
        }
        __syncthreads();
        pe = s_pe;
    }

    if (tid == 0) {
        // stable insertion sort of 8 records by sub_id (matches jnp.argsort stable)
        int ord[NPS];
        #pragma unroll
        for (int j = 0; j < NPS; j++) ord[j] = j;
        for (int a = 1; a < NPS; a++) {
            int o = ord[a], key = rec_s[o], bb = a - 1;
            while (bb >= 0 && rec_s[ord[bb]] > key) { ord[bb + 1] = ord[bb]; bb--; }
            ord[bb + 1] = o;
        }
        const float* pp = ps + (size_t)p * NPS;   // patch_select shape (1,P,NP)
        float slots[NPS];
        float factor = 0.0f;
        #pragma unroll
        for (int j = 0; j < NPS; j++) {
            float s = 1.0f / (1.0f + expf(-pp[j]));
            slots[j] = s; factor += s;
        }
        factor += 1e-10f;
        float acc = 0.0f;
        #pragma unroll
        for (int j = 0; j < NPS; j++)
            acc += rec_v[ord[j]] * (slots[j] * (float)NPS / factor);
        out[bp] = acc;                                  // max_activation_slots
        out[BATCH * PNUM + bp] = (float)NPS - acc;      // min_distances
        #pragma unroll
        for (int j = 0; j < NPS; j++)                   // indices_r
            out[2 * BATCH * PNUM + bp * NPS + j] = (float)rec_e[ord[j]];
    }
}

// ---------------------------------------------------------------------------
extern "C" void kernel_launch(void* const* d_in, const int* in_sizes, int n_in,
                              void* d_out, int out_size) {
    (void)in_sizes; (void)n_in; (void)out_size;
    const float* x     = (const float*)d_in[0];   // (32,512,512)
    const float* tmask = (const float*)d_in[1];   // (32,512)
    const float* proto = (const float*)d_in[2];   // (200,512,8)
    const float* psel  = (const float*)d_in[3];   // (1,200,8)
    float* out = (float*)d_out;

    norm_x_kernel<<<MDIM, 128>>>(x);
    proto_prep_kernel<<<PNUM, 256>>>(proto);
    gemm_kernel<<<dim3(NDIM / BN, MDIM / BM), 256>>>(x, tmask);
    select_kernel<<<BATCH * PNUM, 256>>>(psel, out);
}

// round 4
// speedup vs baseline: 1.0455x; 1.0455x over previous
#include <cuda_runtime.h>
#include <math.h>

#define BATCH 32
#define TLEN  512
#define DDIM  512
#define PNUM  200
#define NPS   8
#define MDIM  (BATCH*TLEN)   // 16384
#define NDIM  (PNUM*NPS)     // 1600
#define NPAD  1664           // 13 * 128, padded N for the GEMM
#define NEGC  (-100000.0f)

// Scratch (static device globals — allocation-free per harness rules)
__device__ float g_dist[(size_t)MDIM * NPAD];   // ~109 MB
__device__ float g_pT[(size_t)DDIM * NPAD];     // normalized prototypes, [k][n] (pad cols stay 0)
__device__ float g_invnx[MDIM];

// ---------------------------------------------------------------------------
// Kernel 1: inverse L2 norm of each x row (m = b*T + t), 128 threads/row
// ---------------------------------------------------------------------------
__global__ void norm_x_kernel(const float* __restrict__ x) {
    int m = blockIdx.x;
    const float4* row = (const float4*)(x + (size_t)m * DDIM);
    float4 v = row[threadIdx.x];
    float s = v.x*v.x + v.y*v.y + v.z*v.z + v.w*v.w;
    #pragma unroll
    for (int o = 16; o; o >>= 1) s += __shfl_down_sync(0xffffffffu, s, o);
    __shared__ float ws[4];
    if ((threadIdx.x & 31) == 0) ws[threadIdx.x >> 5] = s;
    __syncthreads();
    if (threadIdx.x == 0) {
        float t = ws[0] + ws[1] + ws[2] + ws[3];
        g_invnx[m] = 1.0f / fmaxf(sqrtf(t), 1e-12f);
    }
}

// ---------------------------------------------------------------------------
// Kernel 2: normalize prototypes over d and write transposed [k][n] matrix
// ---------------------------------------------------------------------------
__global__ void proto_prep_kernel(const float* __restrict__ proto) {
    int p = blockIdx.x;
    __shared__ float sp[DDIM * NPS];   // 16 KB
    __shared__ float sinv[NPS];
    const float* base = proto + (size_t)p * DDIM * NPS;
    for (int idx = threadIdx.x; idx < DDIM * NPS; idx += blockDim.x)
        sp[idx] = base[idx];
    __syncthreads();
    int w = threadIdx.x >> 5, lane = threadIdx.x & 31;
    if (w < NPS) {
        float s = 0.0f;
        for (int d = lane; d < DDIM; d += 32) { float v = sp[d*NPS + w]; s += v * v; }
        #pragma unroll
        for (int o = 16; o; o >>= 1) s += __shfl_down_sync(0xffffffffu, s, o);
        if (lane == 0) sinv[w] = 1.0f / fmaxf(sqrtf(s), 1e-12f);
    }
    __syncthreads();
    for (int idx = threadIdx.x; idx < DDIM * NPS; idx += blockDim.x) {
        int d = idx >> 3, i = idx & 7;
        g_pT[(size_t)d * NPAD + p * NPS + i] = sp[idx] * sinv[i];
    }
}

// ---------------------------------------------------------------------------
// Kernel 3: fp32 GEMM, scalar FFMA. 128x128x16 tile, 256 threads, 8x8/thread.
// dist[m][n] = (x[m,:] . pT[:,n]) * invnx[m], timeline-masked.
// ---------------------------------------------------------------------------
#define BM 128
#define BN 128
#define BK 16

__global__ void __launch_bounds__(256, 2)
gemm_kernel(const float* __restrict__ X, const float* __restrict__ tmask) {
    __shared__ __align__(16) float As[BK][BM + 4];
    __shared__ __align__(16) float Bs[BK][BN];
    int bm = blockIdx.y * BM, bn = blockIdx.x * BN;
    int tid = (int)threadIdx.x;
    int r = tid >> 4;        // rows r*8 .. r*8+7
    int c = tid & 15;        // cols c*8 .. c*8+7

    float acc[8][8];
    #pragma unroll
    for (int i = 0; i < 8; i++)
        #pragma unroll
        for (int j = 0; j < 8; j++) acc[i][j] = 0.0f;

    for (int k0 = 0; k0 < DDIM; k0 += BK) {
        #pragma unroll
        for (int q = 0; q < 2; q++) {
            int idx = tid + q * 256;
            int row = idx >> 2, kq = (idx & 3) << 2;
            float4 v = *(const float4*)(X + (size_t)(bm + row) * DDIM + k0 + kq);
            As[kq + 0][row] = v.x; As[kq + 1][row] = v.y;
            As[kq + 2][row] = v.z; As[kq + 3][row] = v.w;
        }
        #pragma unroll
        for (int q = 0; q < 2; q++) {
            int idx = tid + q * 256;
            int kk = idx >> 5, nq = (idx & 31) << 2;
            *(float4*)&Bs[kk][nq] = *(const float4*)(g_pT + (size_t)(k0 + kk) * NPAD + bn + nq);
        }
        __syncthreads();
        #pragma unroll
        for (int kk = 0; kk < BK; kk++) {
            float a[8], b[8];
            *(float4*)&a[0] = *(const float4*)&As[kk][r * 8];
            *(float4*)&a[4] = *(const float4*)&As[kk][r * 8 + 4];
            *(float4*)&b[0] = *(const float4*)&Bs[kk][c * 8];
            *(float4*)&b[4] = *(const float4*)&Bs[kk][c * 8 + 4];
            #pragma unroll
            for (int i = 0; i < 8; i++)
                #pragma unroll
                for (int j = 0; j < 8; j++)
                    acc[i][j] = fmaf(a[i], b[j], acc[i][j]);
        }
        __syncthreads();
    }

    #pragma unroll
    for (int i = 0; i < 8; i++) {
        int gm = bm + r * 8 + i;
        float sx = g_invnx[gm];
        float tm = tmask[gm];
        float o[8];
        #pragma unroll
        for (int j = 0; j < 8; j++)
            o[j] = acc[i][j] * sx * tm + (1.0f - tm) * NEGC;
        float* dp = g_dist + (size_t)gm * NPAD + bn + c * 8;
        *(float4*)(dp)     = make_float4(o[0], o[1], o[2], o[3]);
        *(float4*)(dp + 4) = make_float4(o[4], o[5], o[6], o[7]);
    }
}

// ---------------------------------------------------------------------------
// Kernel 4: greedy selection per (b,p). Full scan at it=0 computes BOTH the
// raw argmax (it-0 pick) and the quantized argmax of fl(v + NEG) (fallback
// pick — reference adds NEG in fp32, quantizing values into 0.0078 bins and
// breaking the resulting ties lexicographically by (i,t)). Iterations 1..7
// scan only the adjacency window (<=7 t positions) with one warp.
// ---------------------------------------------------------------------------
__global__ void __launch_bounds__(256)
select_kernel(const float* __restrict__ ps, float* __restrict__ out) {
    int bp = blockIdx.x;            // b*P + p
    int b = bp / PNUM, p = bp % PNUM;
    __shared__ float ds[TLEN * NPS];            // 16 KB dist tile [t][i]
    __shared__ unsigned char mact[TLEN];
    __shared__ float wv[8], wqv[8];
    __shared__ int   wk[8], wqk[8];
    __shared__ float s_gqv;   // fallback value: quantized max fl(v+NEG)
    __shared__ int   s_gqk;   // fallback key
    __shared__ int   s_pe;
    __shared__ int   s_msub;
    __shared__ float rec_v[NPS];
    __shared__ int   rec_e[NPS];
    __shared__ int   rec_s[NPS];
    int tid = (int)threadIdx.x;
    int lane = tid & 31;

    const float* gd = g_dist + (size_t)b * TLEN * NPAD + (size_t)p * NPS;
    for (int idx = tid; idx < TLEN * NPS / 4; idx += 256) {
        int t = idx >> 1, h = (idx & 1) << 2;
        *(float4*)&ds[t * NPS + h] = *(const float4*)(gd + (size_t)t * NPAD + h);
    }
    for (int t = tid; t < TLEN; t += 256) mact[t] = 1;
    __syncthreads();

    // ---- iteration 0: full scan; dual reduction (raw + quantized(+NEG)) ----
    {
        float bv = -INFINITY, qv = -INFINITY;
        int   bk = 0x7fffffff, qk = 0x7fffffff;
        #pragma unroll
        for (int q = 0; q < 2; q++) {
            int t = tid + q * 256;
            float4 lo = *(float4*)&ds[t * NPS];
            float4 hi = *(float4*)&ds[t * NPS + 4];
            float vv[8] = {lo.x, lo.y, lo.z, lo.w, hi.x, hi.y, hi.z, hi.w};
            #pragma unroll
            for (int i = 0; i < NPS; i++) {
                float v = vv[i];
                int k = (i << 9) | t;
                if (v > bv || (v == bv && k < bk)) { bv = v; bk = k; }
                float qq = v + NEGC;   // fp32-rounded, as the reference computes
                if (qq > qv || (qq == qv && k < qk)) { qv = qq; qk = k; }
            }
        }
        #pragma unroll
        for (int o = 16; o; o >>= 1) {
            float ov = __shfl_down_sync(0xffffffffu, bv, o);
            int   ok = __shfl_down_sync(0xffffffffu, bk, o);
            if (ov > bv || (ov == bv && ok < bk)) { bv = ov; bk = ok; }
            float oqv = __shfl_down_sync(0xffffffffu, qv, o);
            int   oqk = __shfl_down_sync(0xffffffffu, qk, o);
            if (oqv > qv || (oqv == qv && oqk < qk)) { qv = oqv; qk = oqk; }
        }
        if (lane == 0) {
            wv[tid >> 5] = bv; wk[tid >> 5] = bk;
            wqv[tid >> 5] = qv; wqk[tid >> 5] = qk;
        }
        __syncthreads();
        if (tid == 0) {
            float fv = wv[0]; int fk = wk[0];
            float fqv = wqv[0]; int fqk = wqk[0];
            #pragma unroll
            for (int w = 1; w < 8; w++) {
                if (wv[w] > fv || (wv[w] == fv && wk[w] < fk)) { fv = wv[w]; fk = wk[w]; }
                if (wqv[w] > fqv || (wqv[w] == fqv && wqk[w] < fqk)) { fqv = wqv[w]; fqk = wqk[w]; }
            }
            int t0 = fk & (TLEN - 1), i0 = fk >> 9;
            mact[t0] = 0;
            s_msub = 0xFF & ~(1 << i0);
            s_pe = t0;
            s_gqv = fqv; s_gqk = fqk;
            rec_v[0] = fv; rec_e[0] = t0; rec_s[0] = i0;
        }
        __syncthreads();
    }

    // ---- iterations 1..7: warp 0 over the adjacency window ----
    if (tid < 32) {
        int pe = s_pe;
        int msub = s_msub;
        float gqv = s_gqv;
        int   gqk = s_gqk;
        for (int it = 1; it < NPS; it++) {
            int wlo = (it == 1) ? max(pe - 3, 0) : (pe + 1);
            int whi = min(pe + 3, TLEN - 1);
            int cnt = (whi >= wlo) ? (whi - wlo + 1) * NPS : 0;
            float bv = -INFINITY;
            int   bk = 0x7fffffff;
            for (int q = lane; q < cnt; q += 32) {
                int t = wlo + (q >> 3), i = q & 7;
                if (mact[t] && ((msub >> i) & 1)) {
                    float v = ds[t * NPS + i];
                    int k = (i << 9) | t;
                    if (v > bv || (v == bv && k < bk)) { bv = v; bk = k; }
                }
            }
            // butterfly reduce so all lanes hold the winner
            #pragma unroll
            for (int o = 16; o; o >>= 1) {
                float ov = __shfl_xor_sync(0xffffffffu, bv, o);
                int   ok = __shfl_xor_sync(0xffffffffu, bk, o);
                if (ov > bv || (ov == bv && ok < bk)) { bv = ov; bk = ok; }
            }
            float recv;
            if (bk == 0x7fffffff) {
                // no valid candidate: reference sees dm = fl(dist + NEG) everywhere
                // -> quantized argmax with (i,t) tie-break, precomputed at it 0
                bk = gqk;
                recv = gqv;
            } else {
                recv = bv;
            }
            int tt = bk & (TLEN - 1), ii = bk >> 9;
            if (lane == 0) {
                mact[tt] = 0;
                rec_v[it] = recv; rec_e[it] = tt; rec_s[it] = ii;
            }
            msub &= ~(1 << ii);
            pe = tt;
            __syncwarp();
        }
    }
    __syncthreads();

    if (tid == 0) {
        // stable insertion sort of 8 records by sub_id (matches stable argsort)
        int ord[NPS];
        #pragma unroll
        for (int j = 0; j < NPS; j++) ord[j] = j;
        for (int a = 1; a < NPS; a++) {
            int o = ord[a], key = rec_s[o], bb = a - 1;
            while (bb >= 0 && rec_s[ord[bb]] > key) { ord[bb + 1] = ord[bb]; bb--; }
            ord[bb + 1] = o;
        }
        const float* pp = ps + (size_t)p * NPS;   // patch_select shape (1,P,NP)
        float slots[NPS];
        float factor = 0.0f;
        #pragma unroll
        for (int j = 0; j < NPS; j++) {
            float s = 1.0f / (1.0f + expf(-pp[j]));
            slots[j] = s; factor += s;
        }
        factor += 1e-10f;
        float acc = 0.0f;
        #pragma unroll
        for (int j = 0; j < NPS; j++)
            acc += rec_v[ord[j]] * (slots[j] * (float)NPS / factor);
        out[bp] = acc;                                  // max_activation_slots
        out[BATCH * PNUM + bp] = (float)NPS - acc;      // min_distances
        #pragma unroll
        for (int j = 0; j < NPS; j++)                   // indices_r
            out[2 * BATCH * PNUM + bp * NPS + j] = (float)rec_e[ord[j]];
    }
}

// ---------------------------------------------------------------------------
extern "C" void kernel_launch(void* const* d_in, const int* in_sizes, int n_in,
                              void* d_out, int out_size) {
    (void)in_sizes; (void)n_in; (void)out_size;
    const float* x     = (const float*)d_in[0];   // (32,512,512)
    const float* tmask = (const float*)d_in[1];   // (32,512)
    const float* proto = (const float*)d_in[2];   // (200,512,8)
    const float* psel  = (const float*)d_in[3];   // (1,200,8)
    float* out = (float*)d_out;

    norm_x_kernel<<<MDIM, 128>>>(x);
    proto_prep_kernel<<<PNUM, 256>>>(proto);
    gemm_kernel<<<dim3(NPAD / BN, MDIM / BM), 256>>>(x, tmask);
    select_kernel<<<BATCH * PNUM, 256>>>(psel, out);
}

// round 6
// speedup vs baseline: 1.5455x; 1.4783x over previous
#include <cuda_runtime.h>
#include <cuda_bf16.h>
#include <math.h>
#include <cstdint>

#define BATCH 32
#define TLEN  512
#define DDIM  512
#define PNUM  200
#define NPS   8
#define MDIM  (BATCH*TLEN)   // 16384
#define NDIM  (PNUM*NPS)     // 1600
#define NPAD  1664           // 13 * 128
#define KEXP  (6*DDIM)       // 3072 expanded K for bf16x6 split
#define NEGC  (-100000.0f)

// ---- scratch (static device globals; allocation-free per harness rules) ----
__device__ float g_dist[(size_t)MDIM * NPAD];                 // ~109 MB
__device__ __nv_bfloat16 g_Aexp[(size_t)MDIM * KEXP];         // ~101 MB
__device__ __nv_bfloat16 g_Bexp[(size_t)NPAD * KEXP];         // ~10 MB

// ---------------------------------------------------------------------------
// Kernel 1: normalize x rows, bf16 3-way split, write expanded A blocks
// A-side block pattern over products (hh,hm,hl,mh,mm,lh): [h, h, h, m, m, l]
// ---------------------------------------------------------------------------
__global__ void split_x_kernel(const float* __restrict__ x) {
    int m = blockIdx.x;
    int t = threadIdx.x;           // 128 threads, 4 elems each
    const float4* row = (const float4*)(x + (size_t)m * DDIM);
    float4 v = row[t];
    float s = v.x*v.x + v.y*v.y + v.z*v.z + v.w*v.w;
    #pragma unroll
    for (int o = 16; o; o >>= 1) s += __shfl_down_sync(0xffffffffu, s, o);
    __shared__ float ws[4];
    __shared__ float sinv;
    if ((t & 31) == 0) ws[t >> 5] = s;
    __syncthreads();
    if (t == 0) sinv = 1.0f / fmaxf(sqrtf(ws[0] + ws[1] + ws[2] + ws[3]), 1e-12f);
    __syncthreads();
    float inv = sinv;
    float xv[4] = {v.x * inv, v.y * inv, v.z * inv, v.w * inv};
    __nv_bfloat16 h[4], mm[4], l[4];
    #pragma unroll
    for (int j = 0; j < 4; j++) {
        h[j] = __float2bfloat16(xv[j]);
        float r1 = xv[j] - __bfloat162float(h[j]);
        mm[j] = __float2bfloat16(r1);
        float r2 = r1 - __bfloat162float(mm[j]);
        l[j] = __float2bfloat16(r2);
    }
    __nv_bfloat162 hp0(h[0], h[1]), hp1(h[2], h[3]);
    __nv_bfloat162 mp0(mm[0], mm[1]), mp1(mm[2], mm[3]);
    __nv_bfloat162 lp0(l[0], l[1]), lp1(l[2], l[3]);
    __nv_bfloat16* base = g_Aexp + (size_t)m * KEXP + 4 * t;
    #pragma unroll
    for (int b = 0; b < 3; b++) {   // blocks 0,1,2 = h
        *(__nv_bfloat162*)(base + b * DDIM)     = hp0;
        *(__nv_bfloat162*)(base + b * DDIM + 2) = hp1;
    }
    #pragma unroll
    for (int b = 3; b < 5; b++) {   // blocks 3,4 = m
        *(__nv_bfloat162*)(base + b * DDIM)     = mp0;
        *(__nv_bfloat162*)(base + b * DDIM + 2) = mp1;
    }
    *(__nv_bfloat162*)(base + 5 * DDIM)     = lp0;   // block 5 = l
    *(__nv_bfloat162*)(base + 5 * DDIM + 2) = lp1;
}

// ---------------------------------------------------------------------------
// Kernel 2: normalize prototypes, bf16 split, expanded B rows [n][KEXP]
// B-side block pattern: [h, m, l, h, m, h]. Pad rows (n>=1600) zeroed.
// ---------------------------------------------------------------------------
__global__ void split_proto_kernel(const float* __restrict__ proto) {
    int p = blockIdx.x;
    int tid = (int)threadIdx.x;
    if (p >= PNUM) {   // zero pad rows
        size_t base = (size_t)p * NPS * KEXP;
        __nv_bfloat162 z(__nv_bfloat16(0.f), __nv_bfloat16(0.f));
        for (int idx = tid; idx < NPS * KEXP / 2; idx += 256)
            ((__nv_bfloat162*)(g_Bexp + base))[idx] = z;
        return;
    }
    __shared__ float sp[DDIM * NPS];   // 16 KB
    __shared__ float sinv[NPS];
    const float* base = proto + (size_t)p * DDIM * NPS;
    for (int idx = tid; idx < DDIM * NPS; idx += 256) sp[idx] = base[idx];
    __syncthreads();
    int w = tid >> 5, lane = tid & 31;
    if (w < NPS) {
        float s = 0.0f;
        for (int d = lane; d < DDIM; d += 32) { float v = sp[d*NPS + w]; s += v*v; }
        #pragma unroll
        for (int o = 16; o; o >>= 1) s += __shfl_down_sync(0xffffffffu, s, o);
        if (lane == 0) sinv[w] = 1.0f / fmaxf(sqrtf(s), 1e-12f);
    }
    __syncthreads();
    for (int idx = tid; idx < NPS * DDIM; idx += 256) {
        int i = idx >> 9, d = idx & (DDIM - 1);
        float v = sp[d * NPS + i] * sinv[i];
        __nv_bfloat16 h = __float2bfloat16(v);
        float r1 = v - __bfloat162float(h);
        __nv_bfloat16 m = __float2bfloat16(r1);
        float r2 = r1 - __bfloat162float(m);
        __nv_bfloat16 l = __float2bfloat16(r2);
        __nv_bfloat16* dst = g_Bexp + (size_t)(p * NPS + i) * KEXP + d;
        dst[0 * DDIM] = h;  // block 0: h
        dst[1 * DDIM] = m;  // block 1: m
        dst[2 * DDIM] = l;  // block 2: l
        dst[3 * DDIM] = h;  // block 3: h
        dst[4 * DDIM] = m;  // block 4: m
        dst[5 * DDIM] = h;  // block 5: h
    }
}

// ---------------------------------------------------------------------------
// Kernel 3: bf16 GEMM via mma.sync (HMMA, sm_80 baseline PTX).
// CTA 128x128, BK=64, 8 warps (warp tile 64x32), cp.async double buffer.
// dist = Aexp @ Bexp^T, timeline-masked on store.
// ---------------------------------------------------------------------------
#define BM 128
#define BN 128
#define BK 64
#define KITERS (KEXP / BK)      // 48
#define STAGE_A_BYTES (BM * BK * 2)   // 16384
#define STAGE_B_BYTES (BN * BK * 2)   // 16384
#define GEMM_SMEM (2 * (STAGE_A_BYTES + STAGE_B_BYTES))  // 65536

__device__ __forceinline__ uint32_t smem_to_u32(const void* p) {
    uint32_t a;
    asm("{ .reg .u64 t; cvta.to.shared.u64 t, %1; cvt.u32.u64 %0, t; }"
        : "=r"(a) : "l"(p));
    return a;
}
#define CP_ASYNC16(saddr, gptr) \
    asm volatile("cp.async.cg.shared.global [%0], [%1], 16;" \
        :: "r"((uint32_t)(saddr)), "l"(gptr))
#define CP_COMMIT() asm volatile("cp.async.commit_group;" ::: "memory")
#define CP_WAIT(n)  asm volatile("cp.async.wait_group %0;" :: "n"(n) : "memory")

__device__ __forceinline__ void ldsm_x4(uint32_t (&r)[4], uint32_t addr) {
    asm volatile("ldmatrix.sync.aligned.m8n8.x4.shared.b16 {%0,%1,%2,%3}, [%4];"
        : "=r"(r[0]), "=r"(r[1]), "=r"(r[2]), "=r"(r[3]) : "r"(addr));
}
__device__ __forceinline__ void mma16816(float (&d)[4], const uint32_t (&a)[4],
                                         uint32_t b0, uint32_t b1) {
    asm volatile(
        "mma.sync.aligned.m16n8k16.row.col.f32.bf16.bf16.f32 "
        "{%0,%1,%2,%3}, {%4,%5,%6,%7}, {%8,%9}, {%0,%1,%2,%3};"
        : "+f"(d[0]), "+f"(d[1]), "+f"(d[2]), "+f"(d[3])
        : "r"(a[0]), "r"(a[1]), "r"(a[2]), "r"(a[3]), "r"(b0), "r"(b1));
}

__global__ void __launch_bounds__(256)
gemm_mma_kernel(const float* __restrict__ tmask) {
    extern __shared__ __align__(128) char smem[];
    uint32_t sb = smem_to_u32(smem);
    const uint32_t aB[2] = {sb, sb + STAGE_A_BYTES};
    const uint32_t bB[2] = {sb + 2 * STAGE_A_BYTES, sb + 2 * STAGE_A_BYTES + STAGE_B_BYTES};

    int tid = (int)threadIdx.x;
    int wid = tid >> 5, lane = tid & 31;
    int bm = blockIdx.y * BM, bn = blockIdx.x * BN;
    int wm = (wid >> 2) * 64;      // warp m offset (0 / 64)
    int wn = (wid & 3) * 32;       // warp n offset (0/32/64/96)

    // cp.async one BK=64 stage: 8 x 16B chunks per row, SW128 xor swizzle
    auto load_stage = [&](int kc, int s) {
        const __nv_bfloat16* ga = g_Aexp + (size_t)bm * KEXP + kc * BK;
        const __nv_bfloat16* gb = g_Bexp + (size_t)bn * KEXP + kc * BK;
        #pragma unroll
        for (int q = 0; q < 4; q++) {
            int idx = tid + q * 256;
            int row = idx >> 3, ch = idx & 7;
            uint32_t so = row * 128 + (uint32_t)((ch ^ (row & 7)) << 4);
            CP_ASYNC16(aB[s] + so, ga + (size_t)row * KEXP + ch * 8);
        }
        #pragma unroll
        for (int q = 0; q < 4; q++) {
            int idx = tid + q * 256;
            int row = idx >> 3, ch = idx & 7;
            uint32_t so = row * 128 + (uint32_t)((ch ^ (row & 7)) << 4);
            CP_ASYNC16(bB[s] + so, gb + (size_t)row * KEXP + ch * 8);
        }
    };

    float d[4][4][4];
    #pragma unroll
    for (int i = 0; i < 4; i++)
        #pragma unroll
        for (int j = 0; j < 4; j++)
            #pragma unroll
            for (int q = 0; q < 4; q++) d[i][j][q] = 0.0f;

    load_stage(0, 0); CP_COMMIT();
    load_stage(1, 1); CP_COMMIT();

    for (int kc = 0; kc < KITERS; kc++) {
        int s = kc & 1;
        CP_WAIT(1);
        __syncthreads();
        #pragma unroll
        for (int ks = 0; ks < 4; ks++) {
            // A fragments: 4 x m16k16
            uint32_t a[4][4];
            #pragma unroll
            for (int fm = 0; fm < 4; fm++) {
                int r = wm + fm * 16 + (lane & 15);
                int c = ks * 2 + (lane >> 4);
                ldsm_x4(a[fm], aB[s] + r * 128 + (uint32_t)((c ^ (r & 7)) << 4));
            }
            // B fragments: 2 x (k16 x n16) -> regs [b0(n0-7), b1(n0-7), b0(n8-15), b1(n8-15)]
            uint32_t bb[2][4];
            #pragma unroll
            for (int g = 0; g < 2; g++) {
                int r = wn + g * 16 + (lane & 7) + ((lane >> 4) << 3);
                int c = ks * 2 + ((lane >> 3) & 1);
                ldsm_x4(bb[g], bB[s] + r * 128 + (uint32_t)((c ^ (r & 7)) << 4));
            }
            #pragma unroll
            for (int fm = 0; fm < 4; fm++)
                #pragma unroll
                for (int fn = 0; fn < 4; fn++)
                    mma16816(d[fm][fn], a[fm], bb[fn >> 1][(fn & 1) * 2],
                             bb[fn >> 1][(fn & 1) * 2 + 1]);
        }
        __syncthreads();
        if (kc + 2 < KITERS) { load_stage(kc + 2, s); CP_COMMIT(); }
    }

    // epilogue: d[fm][fn]: lane gid=lane>>2 (m), tig=lane&3 (n pair)
    int gid = lane >> 2, tig = lane & 3;
    #pragma unroll
    for (int fm = 0; fm < 4; fm++) {
        int m0 = bm + wm + fm * 16 + gid;
        int m1 = m0 + 8;
        float tm0 = tmask[m0], tm1 = tmask[m1];
        float na0 = (1.0f - tm0) * NEGC, na1 = (1.0f - tm1) * NEGC;
        #pragma unroll
        for (int fn = 0; fn < 4; fn++) {
            int n = bn + wn + fn * 8 + tig * 2;
            float2 o0, o1;
            o0.x = d[fm][fn][0] * tm0 + na0;
            o0.y = d[fm][fn][1] * tm0 + na0;
            o1.x = d[fm][fn][2] * tm1 + na1;
            o1.y = d[fm][fn][3] * tm1 + na1;
            *(float2*)(g_dist + (size_t)m0 * NPAD + n) = o0;
            *(float2*)(g_dist + (size_t)m1 * NPAD + n) = o1;
        }
    }
}

// ---------------------------------------------------------------------------
// Kernel 4: greedy selection per (b,p). Full scan at it=0 (raw + quantized
// fallback argmax), then windowed iterations 1..7 with one warp.
// ---------------------------------------------------------------------------
__global__ void __launch_bounds__(256)
select_kernel(const float* __restrict__ ps, float* __restrict__ out) {
    int bp = blockIdx.x;
    int b = bp / PNUM, p = bp % PNUM;
    __shared__ float ds[TLEN * NPS];
    __shared__ unsigned char mact[TLEN];
    __shared__ float wv[8], wqv[8];
    __shared__ int   wk[8], wqk[8];
    __shared__ float s_gqv;
    __shared__ int   s_gqk;
    __shared__ int   s_pe;
    __shared__ int   s_msub;
    __shared__ float rec_v[NPS];
    __shared__ int   rec_e[NPS];
    __shared__ int   rec_s[NPS];
    int tid = (int)threadIdx.x;
    int lane = tid & 31;

    const float* gd = g_dist + (size_t)b * TLEN * NPAD + (size_t)p * NPS;
    for (int idx = tid; idx < TLEN * NPS / 4; idx += 256) {
        int t = idx >> 1, h = (idx & 1) << 2;
        *(float4*)&ds[t * NPS + h] = *(const float4*)(gd + (size_t)t * NPAD + h);
    }
    for (int t = tid; t < TLEN; t += 256) mact[t] = 1;
    __syncthreads();

    {
        float bv = -INFINITY, qv = -INFINITY;
        int   bk = 0x7fffffff, qk = 0x7fffffff;
        #pragma unroll
        for (int q = 0; q < 2; q++) {
            int t = tid + q * 256;
            float4 lo = *(float4*)&ds[t * NPS];
            float4 hi = *(float4*)&ds[t * NPS + 4];
            float vv[8] = {lo.x, lo.y, lo.z, lo.w, hi.x, hi.y, hi.z, hi.w};
            #pragma unroll
            for (int i = 0; i < NPS; i++) {
                float v = vv[i];
                int k = (i << 9) | t;
                if (v > bv || (v == bv && k < bk)) { bv = v; bk = k; }
                float qq = v + NEGC;
                if (qq > qv || (qq == qv && k < qk)) { qv = qq; qk = k; }
            }
        }
        #pragma unroll
        for (int o = 16; o; o >>= 1) {
            float ov = __shfl_down_sync(0xffffffffu, bv, o);
            int   ok = __shfl_down_sync(0xffffffffu, bk, o);
            if (ov > bv || (ov == bv && ok < bk)) { bv = ov; bk = ok; }
            float oqv = __shfl_down_sync(0xffffffffu, qv, o);
            int   oqk = __shfl_down_sync(0xffffffffu, qk, o);
            if (oqv > qv || (oqv == qv && oqk < qk)) { qv = oqv; qk = oqk; }
        }
        if (lane == 0) {
            wv[tid >> 5] = bv; wk[tid >> 5] = bk;
            wqv[tid >> 5] = qv; wqk[tid >> 5] = qk;
        }
        __syncthreads();
        if (tid == 0) {
            float fv = wv[0]; int fk = wk[0];
            float fqv = wqv[0]; int fqk = wqk[0];
            #pragma unroll
            for (int w = 1; w < 8; w++) {
                if (wv[w] > fv || (wv[w] == fv && wk[w] < fk)) { fv = wv[w]; fk = wk[w]; }
                if (wqv[w] > fqv || (wqv[w] == fqv && wqk[w] < fqk)) { fqv = wqv[w]; fqk = wqk[w]; }
            }
            int t0 = fk & (TLEN - 1), i0 = fk >> 9;
            mact[t0] = 0;
            s_msub = 0xFF & ~(1 << i0);
            s_pe = t0;
            s_gqv = fqv; s_gqk = fqk;
            rec_v[0] = fv; rec_e[0] = t0; rec_s[0] = i0;
        }
        __syncthreads();
    }

    if (tid < 32) {
        int pe = s_pe;
        int msub = s_msub;
        float gqv = s_gqv;
        int   gqk = s_gqk;
        for (int it = 1; it < NPS; it++) {
            int wlo = (it == 1) ? max(pe - 3, 0) : (pe + 1);
            int whi = min(pe + 3, TLEN - 1);
            int cnt = (whi >= wlo) ? (whi - wlo + 1) * NPS : 0;
            float bv = -INFINITY;
            int   bk = 0x7fffffff;
            for (int q = lane; q < cnt; q += 32) {
                int t = wlo + (q >> 3), i = q & 7;
                if (mact[t] && ((msub >> i) & 1)) {
                    float v = ds[t * NPS + i];
                    int k = (i << 9) | t;
                    if (v > bv || (v == bv && k < bk)) { bv = v; bk = k; }
                }
            }
            #pragma unroll
            for (int o = 16; o; o >>= 1) {
                float ov = __shfl_xor_sync(0xffffffffu, bv, o);
                int   ok = __shfl_xor_sync(0xffffffffu, bk, o);
                if (ov > bv || (ov == bv && ok < bk)) { bv = ov; bk = ok; }
            }
            float recv;
            if (bk == 0x7fffffff) { bk = gqk; recv = gqv; }
            else                  recv = bv;
            int tt = bk & (TLEN - 1), ii = bk >> 9;
            if (lane == 0) {
                mact[tt] = 0;
                rec_v[it] = recv; rec_e[it] = tt; rec_s[it] = ii;
            }
            msub &= ~(1 << ii);
            pe = tt;
            __syncwarp();
        }
    }
    __syncthreads();

    if (tid == 0) {
        int ord[NPS];
        #pragma unroll
        for (int j = 0; j < NPS; j++) ord[j] = j;
        for (int a = 1; a < NPS; a++) {
            int o = ord[a], key = rec_s[o], bb = a - 1;
            while (bb >= 0 && rec_s[ord[bb]] > key) { ord[bb + 1] = ord[bb]; bb--; }
            ord[bb + 1] = o;
        }
        const float* pp = ps + (size_t)p * NPS;
        float slots[NPS];
        float factor = 0.0f;
        #pragma unroll
        for (int j = 0; j < NPS; j++) {
            float s = 1.0f / (1.0f + expf(-pp[j]));
            slots[j] = s; factor += s;
        }
        factor += 1e-10f;
        float acc = 0.0f;
        #pragma unroll
        for (int j = 0; j < NPS; j++)
            acc += rec_v[ord[j]] * (slots[j] * (float)NPS / factor);
        out[bp] = acc;
        out[BATCH * PNUM + bp] = (float)NPS - acc;
        #pragma unroll
        for (int j = 0; j < NPS; j++)
            out[2 * BATCH * PNUM + bp * NPS + j] = (float)rec_e[ord[j]];
    }
}

// ---------------------------------------------------------------------------
extern "C" void kernel_launch(void* const* d_in, const int* in_sizes, int n_in,
                              void* d_out, int out_size) {
    (void)in_sizes; (void)n_in; (void)out_size;
    const float* x     = (const float*)d_in[0];
    const float* tmask = (const float*)d_in[1];
    const float* proto = (const float*)d_in[2];
    const float* psel  = (const float*)d_in[3];
    float* out = (float*)d_out;

    cudaFuncSetAttribute(gemm_mma_kernel,
                         cudaFuncAttributeMaxDynamicSharedMemorySize, GEMM_SMEM);

    split_x_kernel<<<MDIM, 128>>>(x);
    split_proto_kernel<<<NPAD / NPS, 256>>>(proto);
    gemm_mma_kernel<<<dim3(NPAD / BN, MDIM / BM), 256, GEMM_SMEM>>>(tmask);
    select_kernel<<<BATCH * PNUM, 256>>>(psel, out);
}

// round 7
// speedup vs baseline: 2.2346x; 1.4459x over previous
#include <cuda_runtime.h>
#include <cuda_fp16.h>
#include <math.h>
#include <cstdint>

#define BATCH 32
#define TLEN  512
#define DDIM  512
#define PNUM  200
#define NPS   8
#define MDIM  (BATCH*TLEN)   // 16384
#define NDIM  (PNUM*NPS)     // 1600
#define NPAD  1664           // 13 * 128 (GEMM N padding; pad cols never stored)
#define KEXP  (4*DDIM)       // 2048 expanded K for fp16x2 split (hh,hl,lh,ll)
#define NEGC  (-100000.0f)
#define SCALE 2048.0f        // 2^11 operand prescale (keeps fp16 residuals normal)
#define INVSC (1.0f/(SCALE*SCALE))   // 2^-22, exact

// ---- scratch (static device globals; allocation-free per harness rules) ----
__device__ float g_dist[(size_t)BATCH * PNUM * TLEN * NPS];   // [bp][t*8+i], 105 MB
__device__ __half g_Aexp[(size_t)MDIM * KEXP];                // 64 MB
__device__ __half g_Bexp[(size_t)NPAD * KEXP];                // 6.5 MB

// ---------------------------------------------------------------------------
// Kernel 1: normalize x rows, fp16 2-way split (x2048), expanded A blocks
// A block pattern over products (hh,hl,lh,ll): [h, h, l, l]
// ---------------------------------------------------------------------------
__global__ void split_x_kernel(const float* __restrict__ x) {
    int m = blockIdx.x;
    int t = threadIdx.x;           // 128 threads, 4 elems each
    const float4* row = (const float4*)(x + (size_t)m * DDIM);
    float4 v = row[t];
    float s = v.x*v.x + v.y*v.y + v.z*v.z + v.w*v.w;
    #pragma unroll
    for (int o = 16; o; o >>= 1) s += __shfl_down_sync(0xffffffffu, s, o);
    __shared__ float ws[4];
    __shared__ float sinv;
    if ((t & 31) == 0) ws[t >> 5] = s;
    __syncthreads();
    if (t == 0) sinv = 1.0f / fmaxf(sqrtf(ws[0] + ws[1] + ws[2] + ws[3]), 1e-12f);
    __syncthreads();
    float inv = sinv * SCALE;
    float xv[4] = {v.x * inv, v.y * inv, v.z * inv, v.w * inv};
    __half h[4], l[4];
    #pragma unroll
    for (int j = 0; j < 4; j++) {
        h[j] = __float2half(xv[j]);
        float r = xv[j] - __half2float(h[j]);
        l[j] = __float2half(r);
    }
    __half2 hp0(h[0], h[1]), hp1(h[2], h[3]);
    __half2 lp0(l[0], l[1]), lp1(l[2], l[3]);
    __half* base = g_Aexp + (size_t)m * KEXP + 4 * t;
    *(__half2*)(base + 0 * DDIM)     = hp0;   // block 0: h
    *(__half2*)(base + 0 * DDIM + 2) = hp1;
    *(__half2*)(base + 1 * DDIM)     = hp0;   // block 1: h
    *(__half2*)(base + 1 * DDIM + 2) = hp1;
    *(__half2*)(base + 2 * DDIM)     = lp0;   // block 2: l
    *(__half2*)(base + 2 * DDIM + 2) = lp1;
    *(__half2*)(base + 3 * DDIM)     = lp0;   // block 3: l
    *(__half2*)(base + 3 * DDIM + 2) = lp1;
}

// ---------------------------------------------------------------------------
// Kernel 2: normalize prototypes, fp16 split (x2048), expanded B rows [n][KEXP]
// B block pattern: [h, l, h, l]. Pad rows (n >= 1600) zeroed.
// ---------------------------------------------------------------------------
__global__ void split_proto_kernel(const float* __restrict__ proto) {
    int p = blockIdx.x;
    int tid = (int)threadIdx.x;
    if (p >= PNUM) {   // zero pad rows
        size_t base = (size_t)p * NPS * KEXP;
        __half2 z(__half(0.f), __half(0.f));
        for (int idx = tid; idx < NPS * KEXP / 2; idx += 256)
            ((__half2*)(g_Bexp + base))[idx] = z;
        return;
    }
    __shared__ float sp[DDIM * NPS];   // 16 KB
    __shared__ float sinv[NPS];
    const float* base = proto + (size_t)p * DDIM * NPS;
    for (int idx = tid; idx < DDIM * NPS; idx += 256) sp[idx] = base[idx];
    __syncthreads();
    int w = tid >> 5, lane = tid & 31;
    if (w < NPS) {
        float s = 0.0f;
        for (int d = lane; d < DDIM; d += 32) { float v = sp[d*NPS + w]; s += v*v; }
        #pragma unroll
        for (int o = 16; o; o >>= 1) s += __shfl_down_sync(0xffffffffu, s, o);
        if (lane == 0) sinv[w] = 1.0f / fmaxf(sqrtf(s), 1e-12f);
    }
    __syncthreads();
    for (int idx = tid; idx < NPS * DDIM; idx += 256) {
        int i = idx >> 9, d = idx & (DDIM - 1);
        float v = sp[d * NPS + i] * sinv[i] * SCALE;
        __half h = __float2half(v);
        float r = v - __half2float(h);
        __half l = __float2half(r);
        __half* dst = g_Bexp + (size_t)(p * NPS + i) * KEXP + d;
        dst[0 * DDIM] = h;  // block 0: h
        dst[1 * DDIM] = l;  // block 1: l
        dst[2 * DDIM] = h;  // block 2: h
        dst[3 * DDIM] = l;  // block 3: l
    }
}

// ---------------------------------------------------------------------------
// Kernel 3: fp16 GEMM via mma.sync (HMMA). CTA 128x128, BK=64, 3-stage
// cp.async ring, 8 warps (warp tile 64x32).
// dist[bp][t*8+i] = (Aexp @ Bexp^T) * 2^-22, timeline-masked on store.
// ---------------------------------------------------------------------------
#define BM 128
#define BN 128
#define BK 64
#define KITERS (KEXP / BK)            // 32
#define STAGE_BYTES (BM * BK * 2)     // 16384 per operand per stage
#define NSTAGE 3
#define GEMM_SMEM (NSTAGE * 2 * STAGE_BYTES)  // 98304

__device__ __forceinline__ uint32_t smem_to_u32(const void* p) {
    uint32_t a;
    asm("{ .reg .u64 t; cvta.to.shared.u64 t, %1; cvt.u32.u64 %0, t; }"
        : "=r"(a) : "l"(p));
    return a;
}
#define CP_ASYNC16(saddr, gptr) \
    asm volatile("cp.async.cg.shared.global [%0], [%1], 16;" \
        :: "r"((uint32_t)(saddr)), "l"(gptr))
#define CP_COMMIT() asm volatile("cp.async.commit_group;" ::: "memory")
#define CP_WAIT(n)  asm volatile("cp.async.wait_group %0;" :: "n"(n) : "memory")

__device__ __forceinline__ void ldsm_x4(uint32_t (&r)[4], uint32_t addr) {
    asm volatile("ldmatrix.sync.aligned.m8n8.x4.shared.b16 {%0,%1,%2,%3}, [%4];"
        : "=r"(r[0]), "=r"(r[1]), "=r"(r[2]), "=r"(r[3]) : "r"(addr));
}
__device__ __forceinline__ void mma16816(float (&d)[4], const uint32_t (&a)[4],
                                         uint32_t b0, uint32_t b1) {
    asm volatile(
        "mma.sync.aligned.m16n8k16.row.col.f32.f16.f16.f32 "
        "{%0,%1,%2,%3}, {%4,%5,%6,%7}, {%8,%9}, {%0,%1,%2,%3};"
        : "+f"(d[0]), "+f"(d[1]), "+f"(d[2]), "+f"(d[3])
        : "r"(a[0]), "r"(a[1]), "r"(a[2]), "r"(a[3]), "r"(b0), "r"(b1));
}

__global__ void __launch_bounds__(256)
gemm_mma_kernel(const float* __restrict__ tmask) {
    extern __shared__ __align__(128) char smem[];
    uint32_t sb = smem_to_u32(smem);
    uint32_t aB[NSTAGE], bB[NSTAGE];
    #pragma unroll
    for (int s = 0; s < NSTAGE; s++) {
        aB[s] = sb + (uint32_t)s * 2 * STAGE_BYTES;
        bB[s] = aB[s] + STAGE_BYTES;
    }

    int tid = (int)threadIdx.x;
    int wid = tid >> 5, lane = tid & 31;
    int bm = blockIdx.y * BM, bn = blockIdx.x * BN;
    int wm = (wid >> 2) * 64;
    int wn = (wid & 3) * 32;

    auto load_stage = [&](int kc, int s) {
        const __half* ga = g_Aexp + (size_t)bm * KEXP + kc * BK;
        const __half* gb = g_Bexp + (size_t)bn * KEXP + kc * BK;
        #pragma unroll
        for (int q = 0; q < 4; q++) {
            int idx = tid + q * 256;
            int row = idx >> 3, ch = idx & 7;
            uint32_t so = row * 128 + (uint32_t)((ch ^ (row & 7)) << 4);
            CP_ASYNC16(aB[s] + so, ga + (size_t)row * KEXP + ch * 8);
        }
        #pragma unroll
        for (int q = 0; q < 4; q++) {
            int idx = tid + q * 256;
            int row = idx >> 3, ch = idx & 7;
            uint32_t so = row * 128 + (uint32_t)((ch ^ (row & 7)) << 4);
            CP_ASYNC16(bB[s] + so, gb + (size_t)row * KEXP + ch * 8);
        }
    };

    float d[4][4][4];
    #pragma unroll
    for (int i = 0; i < 4; i++)
        #pragma unroll
        for (int j = 0; j < 4; j++)
            #pragma unroll
            for (int q = 0; q < 4; q++) d[i][j][q] = 0.0f;

    load_stage(0, 0); CP_COMMIT();
    load_stage(1, 1); CP_COMMIT();
    load_stage(2, 2); CP_COMMIT();

    int s = 0;
    for (int kc = 0; kc < KITERS; kc++) {
        CP_WAIT(2);
        __syncthreads();
        #pragma unroll
        for (int ks = 0; ks < 4; ks++) {
            uint32_t a[4][4];
            #pragma unroll
            for (int fm = 0; fm < 4; fm++) {
                int r = wm + fm * 16 + (lane & 15);
                int c = ks * 2 + (lane >> 4);
                ldsm_x4(a[fm], aB[s] + r * 128 + (uint32_t)((c ^ (r & 7)) << 4));
            }
            uint32_t bb[2][4];
            #pragma unroll
            for (int g = 0; g < 2; g++) {
                int r = wn + g * 16 + (lane & 7) + ((lane >> 4) << 3);
                int c = ks * 2 + ((lane >> 3) & 1);
                ldsm_x4(bb[g], bB[s] + r * 128 + (uint32_t)((c ^ (r & 7)) << 4));
            }
            #pragma unroll
            for (int fm = 0; fm < 4; fm++)
                #pragma unroll
                for (int fn = 0; fn < 4; fn++)
                    mma16816(d[fm][fn], a[fm], bb[fn >> 1][(fn & 1) * 2],
                             bb[fn >> 1][(fn & 1) * 2 + 1]);
        }
        __syncthreads();
        if (kc + NSTAGE < KITERS) load_stage(kc + NSTAGE, s);
        CP_COMMIT();   // empty groups at the tail keep wait-depth constant
        s = (s == NSTAGE - 1) ? 0 : s + 1;
    }

    // epilogue: scale by 2^-22, timeline mask, store to [bp][t*8+i] layout
    int gid = lane >> 2, tig = lane & 3;
    #pragma unroll
    for (int fm = 0; fm < 4; fm++) {
        int m0 = bm + wm + fm * 16 + gid;
        int m1 = m0 + 8;
        int b = m0 >> 9;              // same for m0, m1
        int t0 = m0 & (TLEN - 1), t1 = m1 & (TLEN - 1);
        float tm0 = tmask[m0], tm1 = tmask[m1];
        float s0 = INVSC * tm0, s1 = INVSC * tm1;
        float na0 = (1.0f - tm0) * NEGC, na1 = (1.0f - tm1) * NEGC;
        #pragma unroll
        for (int fn = 0; fn < 4; fn++) {
            int n = bn + wn + fn * 8 + tig * 2;
            if (n >= NDIM) continue;
            int p = n >> 3, i = n & 7;
            size_t base = ((size_t)(b * PNUM + p) << 12);
            float2 o0, o1;
            o0.x = d[fm][fn][0] * s0 + na0;
            o0.y = d[fm][fn][1] * s0 + na0;
            o1.x = d[fm][fn][2] * s1 + na1;
            o1.y = d[fm][fn][3] * s1 + na1;
            *(float2*)(g_dist + base + (t0 << 3) + i) = o0;
            *(float2*)(g_dist + base + (t1 << 3) + i) = o1;
        }
    }
}

// ---------------------------------------------------------------------------
// Kernel 4: greedy selection per (b,p). Contiguous 16 KB tile load, full scan
// at it=0 (raw + quantized fallback argmax), windowed iterations 1..7.
// ---------------------------------------------------------------------------
__global__ void __launch_bounds__(256)
select_kernel(const float* __restrict__ ps, float* __restrict__ out) {
    int bp = blockIdx.x;
    int p = bp % PNUM;
    __shared__ float ds[TLEN * NPS];
    __shared__ unsigned char mact[TLEN];
    __shared__ float wv[8], wqv[8];
    __shared__ int   wk[8], wqk[8];
    __shared__ float s_gqv;
    __shared__ int   s_gqk;
    __shared__ int   s_pe;
    __shared__ int   s_msub;
    __shared__ float rec_v[NPS];
    __shared__ int   rec_e[NPS];
    __shared__ int   rec_s[NPS];
    int tid = (int)threadIdx.x;
    int lane = tid & 31;

    const float4* gd4 = (const float4*)(g_dist + ((size_t)bp << 12));
    float4* ds4 = (float4*)ds;
    #pragma unroll
    for (int q = 0; q < 4; q++) ds4[tid + q * 256] = gd4[tid + q * 256];
    for (int t = tid; t < TLEN; t += 256) mact[t] = 1;
    __syncthreads();

    {
        float bv = -INFINITY, qv = -INFINITY;
        int   bk = 0x7fffffff, qk = 0x7fffffff;
        #pragma unroll
        for (int q = 0; q < 2; q++) {
            int t = tid + q * 256;
            float4 lo = *(float4*)&ds[t * NPS];
            float4 hi = *(float4*)&ds[t * NPS + 4];
            float vv[8] = {lo.x, lo.y, lo.z, lo.w, hi.x, hi.y, hi.z, hi.w};
            #pragma unroll
            for (int i = 0; i < NPS; i++) {
                float v = vv[i];
                int k = (i << 9) | t;
                if (v > bv || (v == bv && k < bk)) { bv = v; bk = k; }
                float qq = v + NEGC;
                if (qq > qv || (qq == qv && k < qk)) { qv = qq; qk = k; }
            }
        }
        #pragma unroll
        for (int o = 16; o; o >>= 1) {
            float ov = __shfl_down_sync(0xffffffffu, bv, o);
            int   ok = __shfl_down_sync(0xffffffffu, bk, o);
            if (ov > bv || (ov == bv && ok < bk)) { bv = ov; bk = ok; }
            float oqv = __shfl_down_sync(0xffffffffu, qv, o);
            int   oqk = __shfl_down_sync(0xffffffffu, qk, o);
            if (oqv > qv || (oqv == qv && oqk < qk)) { qv = oqv; qk = oqk; }
        }
        if (lane == 0) {
            wv[tid >> 5] = bv; wk[tid >> 5] = bk;
            wqv[tid >> 5] = qv; wqk[tid >> 5] = qk;
        }
        __syncthreads();
        if (tid == 0) {
            float fv = wv[0]; int fk = wk[0];
            float fqv = wqv[0]; int fqk = wqk[0];
            #pragma unroll
            for (int w = 1; w < 8; w++) {
                if (wv[w] > fv || (wv[w] == fv && wk[w] < fk)) { fv = wv[w]; fk = wk[w]; }
                if (wqv[w] > fqv || (wqv[w] == fqv && wqk[w] < fqk)) { fqv = wqv[w]; fqk = wqk[w]; }
            }
            int t0 = fk & (TLEN - 1), i0 = fk >> 9;
            mact[t0] = 0;
            s_msub = 0xFF & ~(1 << i0);
            s_pe = t0;
            s_gqv = fqv; s_gqk = fqk;
            rec_v[0] = fv; rec_e[0] = t0; rec_s[0] = i0;
        }
        __syncthreads();
    }

    if (tid < 32) {
        int pe = s_pe;
        int msub = s_msub;
        float gqv = s_gqv;
        int   gqk = s_gqk;
        for (int it = 1; it < NPS; it++) {
            int wlo = (it == 1) ? max(pe - 3, 0) : (pe + 1);
            int whi = min(pe + 3, TLEN - 1);
            int cnt = (whi >= wlo) ? (whi - wlo + 1) * NPS : 0;
            float bv = -INFINITY;
            int   bk = 0x7fffffff;
            for (int q = lane; q < cnt; q += 32) {
                int t = wlo + (q >> 3), i = q & 7;
                if (mact[t] && ((msub >> i) & 1)) {
                    float v = ds[t * NPS + i];
                    int k = (i << 9) | t;
                    if (v > bv || (v == bv && k < bk)) { bv = v; bk = k; }
                }
            }
            #pragma unroll
            for (int o = 16; o; o >>= 1) {
                float ov = __shfl_xor_sync(0xffffffffu, bv, o);
                int   ok = __shfl_xor_sync(0xffffffffu, bk, o);
                if (ov > bv || (ov == bv && ok < bk)) { bv = ov; bk = ok; }
            }
            float recv;
            if (bk == 0x7fffffff) { bk = gqk; recv = gqv; }
            else                  recv = bv;
            int tt = bk & (TLEN - 1), ii = bk >> 9;
            if (lane == 0) {
                mact[tt] = 0;
                rec_v[it] = recv; rec_e[it] = tt; rec_s[it] = ii;
            }
            msub &= ~(1 << ii);
            pe = tt;
            __syncwarp();
        }
    }
    __syncthreads();

    if (tid == 0) {
        int ord[NPS];
        #pragma unroll
        for (int j = 0; j < NPS; j++) ord[j] = j;
        for (int a = 1; a < NPS; a++) {
            int o = ord[a], key = rec_s[o], bb = a - 1;
            while (bb >= 0 && rec_s[ord[bb]] > key) { ord[bb + 1] = ord[bb]; bb--; }
            ord[bb + 1] = o;
        }
        const float* pp = ps + (size_t)p * NPS;
        float slots[NPS];
        float factor = 0.0f;
        #pragma unroll
        for (int j = 0; j < NPS; j++) {
            float s = 1.0f / (1.0f + expf(-pp[j]));
            slots[j] = s; factor += s;
        }
        factor += 1e-10f;
        float acc = 0.0f;
        #pragma unroll
        for (int j = 0; j < NPS; j++)
            acc += rec_v[ord[j]] * (slots[j] * (float)NPS / factor);
        out[bp] = acc;
        out[BATCH * PNUM + bp] = (float)NPS - acc;
        #pragma unroll
        for (int j = 0; j < NPS; j++)
            out[2 * BATCH * PNUM + bp * NPS + j] = (float)rec_e[ord[j]];
    }
}

// ---------------------------------------------------------------------------
extern "C" void kernel_launch(void* const* d_in, const int* in_sizes, int n_in,
                              void* d_out, int out_size) {
    (void)in_sizes; (void)n_in; (void)out_size;
    const float* x     = (const float*)d_in[0];
    const float* tmask = (const float*)d_in[1];
    const float* proto = (const float*)d_in[2];
    const float* psel  = (const float*)d_in[3];
    float* out = (float*)d_out;

    cudaFuncSetAttribute(gemm_mma_kernel,
                         cudaFuncAttributeMaxDynamicSharedMemorySize, GEMM_SMEM);

    split_x_kernel<<<MDIM, 128>>>(x);
    split_proto_kernel<<<NPAD / NPS, 256>>>(proto);
    gemm_mma_kernel<<<dim3(NPAD / BN, MDIM / BM), 256, GEMM_SMEM>>>(tmask);
    select_kernel<<<BATCH * PNUM, 256>>>(psel, out);
}

// round 8
// speedup vs baseline: 2.7059x; 1.2109x over previous
#include <cuda_runtime.h>
#include <cuda_fp16.h>
#include <math.h>
#include <cstdint>

#define BATCH 32
#define TLEN  512
#define DDIM  512
#define PNUM  200
#define NPS   8
#define MDIM  (BATCH*TLEN)   // 16384
#define NDIM  (PNUM*NPS)     // 1600
#define NPAD  1664           // 13 * 128 (GEMM N padding; pad cols never stored)
#define NEGC  (-100000.0f)
#define SCALE 2048.0f        // 2^11 operand prescale (keeps fp16 residuals normal)
#define INVSC (1.0f/(SCALE*SCALE))   // 2^-22, exact

// ---- scratch (static device globals; allocation-free per harness rules) ----
__device__ float g_dist[(size_t)BATCH * PNUM * TLEN * NPS];   // [bp][t*8+i], 105 MB
__device__ __half g_Ah[(size_t)MDIM * DDIM];                  // 16 MB
__device__ __half g_Al[(size_t)MDIM * DDIM];                  // 16 MB
__device__ __half g_Bh[(size_t)NPAD * DDIM];                  // 1.6 MB
__device__ __half g_Bl[(size_t)NPAD * DDIM];                  // 1.6 MB

// ---------------------------------------------------------------------------
// Kernel 1: normalize x rows, fp16 2-way split (x2048) -> g_Ah, g_Al
// ---------------------------------------------------------------------------
__global__ void split_x_kernel(const float* __restrict__ x) {
    int m = blockIdx.x;
    int t = threadIdx.x;           // 128 threads, 4 elems each
    const float4* row = (const float4*)(x + (size_t)m * DDIM);
    float4 v = row[t];
    float s = v.x*v.x + v.y*v.y + v.z*v.z + v.w*v.w;
    #pragma unroll
    for (int o = 16; o; o >>= 1) s += __shfl_down_sync(0xffffffffu, s, o);
    __shared__ float ws[4];
    __shared__ float sinv;
    if ((t & 31) == 0) ws[t >> 5] = s;
    __syncthreads();
    if (t == 0) sinv = 1.0f / fmaxf(sqrtf(ws[0] + ws[1] + ws[2] + ws[3]), 1e-12f);
    __syncthreads();
    float inv = sinv * SCALE;
    float xv[4] = {v.x * inv, v.y * inv, v.z * inv, v.w * inv};
    __half h[4], l[4];
    #pragma unroll
    for (int j = 0; j < 4; j++) {
        h[j] = __float2half(xv[j]);
        float r = xv[j] - __half2float(h[j]);
        l[j] = __float2half(r);
    }
    size_t off = (size_t)m * DDIM + 4 * t;
    *(__half2*)(g_Ah + off)     = __half2(h[0], h[1]);
    *(__half2*)(g_Ah + off + 2) = __half2(h[2], h[3]);
    *(__half2*)(g_Al + off)     = __half2(l[0], l[1]);
    *(__half2*)(g_Al + off + 2) = __half2(l[2], l[3]);
}

// ---------------------------------------------------------------------------
// Kernel 2: normalize prototypes, fp16 split (x2048) -> g_Bh, g_Bl [n][512].
// Pad rows (n >= 1600) zeroed.
// ---------------------------------------------------------------------------
__global__ void split_proto_kernel(const float* __restrict__ proto) {
    int p = blockIdx.x;
    int tid = (int)threadIdx.x;
    if (p >= PNUM) {   // zero pad rows
        size_t base = (size_t)p * NPS * DDIM;
        __half2 z(__half(0.f), __half(0.f));
        for (int idx = tid; idx < NPS * DDIM / 2; idx += 256) {
            ((__half2*)(g_Bh + base))[idx] = z;
            ((__half2*)(g_Bl + base))[idx] = z;
        }
        return;
    }
    __shared__ float sp[DDIM * NPS];   // 16 KB
    __shared__ float sinv[NPS];
    const float* base = proto + (size_t)p * DDIM * NPS;
    for (int idx = tid; idx < DDIM * NPS; idx += 256) sp[idx] = base[idx];
    __syncthreads();
    int w = tid >> 5, lane = tid & 31;
    if (w < NPS) {
        float s = 0.0f;
        for (int d = lane; d < DDIM; d += 32) { float v = sp[d*NPS + w]; s += v*v; }
        #pragma unroll
        for (int o = 16; o; o >>= 1) s += __shfl_down_sync(0xffffffffu, s, o);
        if (lane == 0) sinv[w] = 1.0f / fmaxf(sqrtf(s), 1e-12f);
    }
    __syncthreads();
    for (int idx = tid; idx < NPS * DDIM; idx += 256) {
        int i = idx >> 9, d = idx & (DDIM - 1);
        float v = sp[d * NPS + i] * sinv[i] * SCALE;
        __half h = __float2half(v);
        float r = v - __half2float(h);
        __half l = __float2half(r);
        size_t off = (size_t)(p * NPS + i) * DDIM + d;
        g_Bh[off] = h;
        g_Bl[off] = l;
    }
}

// ---------------------------------------------------------------------------
// Kernel 3: fp16 GEMM via mma.sync with register-fragment reuse.
// Per real-k chunk, load A_h/A_l/B_h/B_l once; issue 3 combos (hh, hl, lh)
// from registers (ll dropped: |contribution| ~3e-9, below fp32 noise).
// CTA 128x128, BK=64 real-k, 3-stage ring of 4 buffers.
// dist[bp][t*8+i] = result * 2^-22, timeline-masked on store.
// ---------------------------------------------------------------------------
#define BM 128
#define BN 128
#define BK 64
#define KITERS (DDIM / BK)            // 8
#define BUF_BYTES (BM * BK * 2)       // 16384 per buffer
#define NSTAGE 3
#define GEMM_SMEM (NSTAGE * 4 * BUF_BYTES)  // 196608

__device__ __forceinline__ uint32_t smem_to_u32(const void* p) {
    uint32_t a;
    asm("{ .reg .u64 t; cvta.to.shared.u64 t, %1; cvt.u32.u64 %0, t; }"
        : "=r"(a) : "l"(p));
    return a;
}
#define CP_ASYNC16(saddr, gptr) \
    asm volatile("cp.async.cg.shared.global [%0], [%1], 16;" \
        :: "r"((uint32_t)(saddr)), "l"(gptr))
#define CP_COMMIT() asm volatile("cp.async.commit_group;" ::: "memory")
#define CP_WAIT(n)  asm volatile("cp.async.wait_group %0;" :: "n"(n) : "memory")

__device__ __forceinline__ void ldsm_x4(uint32_t (&r)[4], uint32_t addr) {
    asm volatile("ldmatrix.sync.aligned.m8n8.x4.shared.b16 {%0,%1,%2,%3}, [%4];"
        : "=r"(r[0]), "=r"(r[1]), "=r"(r[2]), "=r"(r[3]) : "r"(addr));
}
__device__ __forceinline__ void mma16816(float (&d)[4], const uint32_t (&a)[4],
                                         uint32_t b0, uint32_t b1) {
    asm volatile(
        "mma.sync.aligned.m16n8k16.row.col.f32.f16.f16.f32 "
        "{%0,%1,%2,%3}, {%4,%5,%6,%7}, {%8,%9}, {%0,%1,%2,%3};"
        : "+f"(d[0]), "+f"(d[1]), "+f"(d[2]), "+f"(d[3])
        : "r"(a[0]), "r"(a[1]), "r"(a[2]), "r"(a[3]), "r"(b0), "r"(b1));
}

__global__ void __launch_bounds__(256)
gemm_mma_kernel(const float* __restrict__ tmask) {
    extern __shared__ __align__(128) char smem[];
    uint32_t sb = smem_to_u32(smem);

    int tid = (int)threadIdx.x;
    int wid = tid >> 5, lane = tid & 31;
    int bm = blockIdx.y * BM, bn = blockIdx.x * BN;
    int wm = (wid >> 2) * 64;
    int wn = (wid & 3) * 32;

    // stage s, buffer w (0=Ah,1=Al,2=Bh,3=Bl)
    auto buf = [&](int s, int w) -> uint32_t {
        return sb + (uint32_t)(s * 4 + w) * BUF_BYTES;
    };

    const __half* gsrc[4] = {g_Ah + (size_t)bm * DDIM, g_Al + (size_t)bm * DDIM,
                             g_Bh + (size_t)bn * DDIM, g_Bl + (size_t)bn * DDIM};

    auto load_stage = [&](int kc, int s) {
        #pragma unroll
        for (int w = 0; w < 4; w++) {
            const __half* g = gsrc[w] + kc * BK;
            uint32_t sbase = buf(s, w);
            #pragma unroll
            for (int q = 0; q < 4; q++) {
                int idx = tid + q * 256;
                int row = idx >> 3, ch = idx & 7;
                uint32_t so = row * 128 + (uint32_t)((ch ^ (row & 7)) << 4);
                CP_ASYNC16(sbase + so, g + (size_t)row * DDIM + ch * 8);
            }
        }
    };

    float d[4][4][4];
    #pragma unroll
    for (int i = 0; i < 4; i++)
        #pragma unroll
        for (int j = 0; j < 4; j++)
            #pragma unroll
            for (int q = 0; q < 4; q++) d[i][j][q] = 0.0f;

    load_stage(0, 0); CP_COMMIT();
    load_stage(1, 1); CP_COMMIT();
    load_stage(2, 2); CP_COMMIT();

    int s = 0;
    for (int kc = 0; kc < KITERS; kc++) {
        CP_WAIT(2);
        __syncthreads();
        uint32_t aHb = buf(s, 0), aLb = buf(s, 1), bHb = buf(s, 2), bLb = buf(s, 3);
        #pragma unroll
        for (int ks = 0; ks < 4; ks++) {
            uint32_t ah[4][4], al[4][4];
            #pragma unroll
            for (int fm = 0; fm < 4; fm++) {
                int r = wm + fm * 16 + (lane & 15);
                int c = ks * 2 + (lane >> 4);
                uint32_t so = r * 128 + (uint32_t)((c ^ (r & 7)) << 4);
                ldsm_x4(ah[fm], aHb + so);
                ldsm_x4(al[fm], aLb + so);
            }
            uint32_t bh[2][4], bl[2][4];
            #pragma unroll
            for (int g = 0; g < 2; g++) {
                int r = wn + g * 16 + (lane & 7) + ((lane >> 4) << 3);
                int c = ks * 2 + ((lane >> 3) & 1);
                uint32_t so = r * 128 + (uint32_t)((c ^ (r & 7)) << 4);
                ldsm_x4(bh[g], bHb + so);
                ldsm_x4(bl[g], bLb + so);
            }
            #pragma unroll
            for (int fm = 0; fm < 4; fm++)
                #pragma unroll
                for (int fn = 0; fn < 4; fn++) {
                    uint32_t bh0 = bh[fn >> 1][(fn & 1) * 2];
                    uint32_t bh1 = bh[fn >> 1][(fn & 1) * 2 + 1];
                    uint32_t bl0 = bl[fn >> 1][(fn & 1) * 2];
                    uint32_t bl1 = bl[fn >> 1][(fn & 1) * 2 + 1];
                    mma16816(d[fm][fn], ah[fm], bh0, bh1);   // hh
                    mma16816(d[fm][fn], ah[fm], bl0, bl1);   // hl
                    mma16816(d[fm][fn], al[fm], bh0, bh1);   // lh
                }
        }
        __syncthreads();
        if (kc + NSTAGE < KITERS) load_stage(kc + NSTAGE, s);
        CP_COMMIT();   // empty groups at the tail keep wait-depth constant
        s = (s == NSTAGE - 1) ? 0 : s + 1;
    }

    // epilogue: scale by 2^-22, timeline mask, store to [bp][t*8+i] layout
    int gid = lane >> 2, tig = lane & 3;
    #pragma unroll
    for (int fm = 0; fm < 4; fm++) {
        int m0 = bm + wm + fm * 16 + gid;
        int m1 = m0 + 8;
        int b = m0 >> 9;              // same for m0, m1
        int t0 = m0 & (TLEN - 1), t1 = m1 & (TLEN - 1);
        float tm0 = tmask[m0], tm1 = tmask[m1];
        float s0 = INVSC * tm0, s1 = INVSC * tm1;
        float na0 = (1.0f - tm0) * NEGC, na1 = (1.0f - tm1) * NEGC;
        #pragma unroll
        for (int fn = 0; fn < 4; fn++) {
            int n = bn + wn + fn * 8 + tig * 2;
            if (n >= NDIM) continue;
            int p = n >> 3, i = n & 7;
            size_t base = ((size_t)(b * PNUM + p) << 12);
            float2 o0, o1;
            o0.x = d[fm][fn][0] * s0 + na0;
            o0.y = d[fm][fn][1] * s0 + na0;
            o1.x = d[fm][fn][2] * s1 + na1;
            o1.y = d[fm][fn][3] * s1 + na1;
            *(float2*)(g_dist + base + (t0 << 3) + i) = o0;
            *(float2*)(g_dist + base + (t1 << 3) + i) = o1;
        }
    }
}

// ---------------------------------------------------------------------------
// Kernel 4: greedy selection per (b,p). Contiguous 16 KB tile load, full scan
// at it=0 (raw + quantized fallback argmax), windowed iterations 1..7.
// ---------------------------------------------------------------------------
__global__ void __launch_bounds__(256)
select_kernel(const float* __restrict__ ps, float* __restrict__ out) {
    int bp = blockIdx.x;
    int p = bp % PNUM;
    __shared__ float ds[TLEN * NPS];
    __shared__ unsigned char mact[TLEN];
    __shared__ float wv[8], wqv[8];
    __shared__ int   wk[8], wqk[8];
    __shared__ float s_gqv;
    __shared__ int   s_gqk;
    __shared__ int   s_pe;
    __shared__ int   s_msub;
    __shared__ float rec_v[NPS];
    __shared__ int   rec_e[NPS];
    __shared__ int   rec_s[NPS];
    int tid = (int)threadIdx.x;
    int lane = tid & 31;

    const float4* gd4 = (const float4*)(g_dist + ((size_t)bp << 12));
    float4* ds4 = (float4*)ds;
    #pragma unroll
    for (int q = 0; q < 4; q++) ds4[tid + q * 256] = gd4[tid + q * 256];
    for (int t = tid; t < TLEN; t += 256) mact[t] = 1;
    __syncthreads();

    {
        float bv = -INFINITY, qv = -INFINITY;
        int   bk = 0x7fffffff, qk = 0x7fffffff;
        #pragma unroll
        for (int q = 0; q < 2; q++) {
            int t = tid + q * 256;
            float4 lo = *(float4*)&ds[t * NPS];
            float4 hi = *(float4*)&ds[t * NPS + 4];
            float vv[8] = {lo.x, lo.y, lo.z, lo.w, hi.x, hi.y, hi.z, hi.w};
            #pragma unroll
            for (int i = 0; i < NPS; i++) {
                float v = vv[i];
                int k = (i << 9) | t;
                if (v > bv || (v == bv && k < bk)) { bv = v; bk = k; }
                float qq = v + NEGC;
                if (qq > qv || (qq == qv && k < qk)) { qv = qq; qk = k; }
            }
        }
        #pragma unroll
        for (int o = 16; o; o >>= 1) {
            float ov = __shfl_down_sync(0xffffffffu, bv, o);
            int   ok = __shfl_down_sync(0xffffffffu, bk, o);
            if (ov > bv || (ov == bv && ok < bk)) { bv = ov; bk = ok; }
            float oqv = __shfl_down_sync(0xffffffffu, qv, o);
            int   oqk = __shfl_down_sync(0xffffffffu, qk, o);
            if (oqv > qv || (oqv == qv && oqk < qk)) { qv = oqv; qk = oqk; }
        }
        if (lane == 0) {
            wv[tid >> 5] = bv; wk[tid >> 5] = bk;
            wqv[tid >> 5] = qv; wqk[tid >> 5] = qk;
        }
        __syncthreads();
        if (tid == 0) {
            float fv = wv[0]; int fk = wk[0];
            float fqv = wqv[0]; int fqk = wqk[0];
            #pragma unroll
            for (int w = 1; w < 8; w++) {
                if (wv[w] > fv || (wv[w] == fv && wk[w] < fk)) { fv = wv[w]; fk = wk[w]; }
                if (wqv[w] > fqv || (wqv[w] == fqv && wqk[w] < fqk)) { fqv = wqv[w]; fqk = wqk[w]; }
            }
            int t0 = fk & (TLEN - 1), i0 = fk >> 9;
            mact[t0] = 0;
            s_msub = 0xFF & ~(1 << i0);
            s_pe = t0;
            s_gqv = fqv; s_gqk = fqk;
            rec_v[0] = fv; rec_e[0] = t0; rec_s[0] = i0;
        }
        __syncthreads();
    }

    if (tid < 32) {
        int pe = s_pe;
        int msub = s_msub;
        float gqv = s_gqv;
        int   gqk = s_gqk;
        for (int it = 1; it < NPS; it++) {
            int wlo = (it == 1) ? max(pe - 3, 0) : (pe + 1);
            int whi = min(pe + 3, TLEN - 1);
            int cnt = (whi >= wlo) ? (whi - wlo + 1) * NPS : 0;
            float bv = -INFINITY;
            int   bk = 0x7fffffff;
            for (int q = lane; q < cnt; q += 32) {
                int t = wlo + (q >> 3), i = q & 7;
                if (mact[t] && ((msub >> i) & 1)) {
                    float v = ds[t * NPS + i];
                    int k = (i << 9) | t;
                    if (v > bv || (v == bv && k < bk)) { bv = v; bk = k; }
                }
            }
            #pragma unroll
            for (int o = 16; o; o >>= 1) {
                float ov = __shfl_xor_sync(0xffffffffu, bv, o);
                int   ok = __shfl_xor_sync(0xffffffffu, bk, o);
                if (ov > bv || (ov == bv && ok < bk)) { bv = ov; bk = ok; }
            }
            float recv;
            if (bk == 0x7fffffff) { bk = gqk; recv = gqv; }
            else                  recv = bv;
            int tt = bk & (TLEN - 1), ii = bk >> 9;
            if (lane == 0) {
                mact[tt] = 0;
                rec_v[it] = recv; rec_e[it] = tt; rec_s[it] = ii;
            }
            msub &= ~(1 << ii);
            pe = tt;
            __syncwarp();
        }
    }
    __syncthreads();

    if (tid == 0) {
        int ord[NPS];
        #pragma unroll
        for (int j = 0; j < NPS; j++) ord[j] = j;
        for (int a = 1; a < NPS; a++) {
            int o = ord[a], key = rec_s[o], bb = a - 1;
            while (bb >= 0 && rec_s[ord[bb]] > key) { ord[bb + 1] = ord[bb]; bb--; }
            ord[bb + 1] = o;
        }
        const float* pp = ps + (size_t)p * NPS;
        float slots[NPS];
        float factor = 0.0f;
        #pragma unroll
        for (int j = 0; j < NPS; j++) {
            float s = 1.0f / (1.0f + expf(-pp[j]));
            slots[j] = s; factor += s;
        }
        factor += 1e-10f;
        float acc = 0.0f;
        #pragma unroll
        for (int j = 0; j < NPS; j++)
            acc += rec_v[ord[j]] * (slots[j] * (float)NPS / factor);
        out[bp] = acc;
        out[BATCH * PNUM + bp] = (float)NPS - acc;
        #pragma unroll
        for (int j = 0; j < NPS; j++)
            out[2 * BATCH * PNUM + bp * NPS + j] = (float)rec_e[ord[j]];
    }
}

// ---------------------------------------------------------------------------
extern "C" void kernel_launch(void* const* d_in, const int* in_sizes, int n_in,
                              void* d_out, int out_size) {
    (void)in_sizes; (void)n_in; (void)out_size;
    const float* x     = (const float*)d_in[0];
    const float* tmask = (const float*)d_in[1];
    const float* proto = (const float*)d_in[2];
    const float* psel  = (const float*)d_in[3];
    float* out = (float*)d_out;

    cudaFuncSetAttribute(gemm_mma_kernel,
                         cudaFuncAttributeMaxDynamicSharedMemorySize, GEMM_SMEM);

    split_x_kernel<<<MDIM, 128>>>(x);
    split_proto_kernel<<<NPAD / NPS, 256>>>(proto);
    gemm_mma_kernel<<<dim3(NPAD / BN, MDIM / BM), 256, GEMM_SMEM>>>(tmask);
    select_kernel<<<BATCH * PNUM, 256>>>(psel, out);
}

// round 9
// speedup vs baseline: 2.9428x; 1.0875x over previous
#include <cuda_runtime.h>
#include <cuda_fp16.h>
#include <math.h>
#include <cstdint>

#define BATCH 32
#define TLEN  512
#define DDIM  512
#define PNUM  200
#define NPS   8
#define MDIM  (BATCH*TLEN)   // 16384
#define NDIM  (PNUM*NPS)     // 1600
#define NPAD  1664           // 13 * 128 (GEMM N padding; pad cols never stored)
#define NEGC  (-100000.0f)
#define SCALE 2048.0f        // 2^11 operand prescale (keeps fp16 residuals normal)
#define INVSC (1.0f/(SCALE*SCALE))   // 2^-22, exact

// ---- scratch (static device globals; allocation-free per harness rules) ----
__device__ float g_dist[(size_t)BATCH * PNUM * TLEN * NPS];   // [bp][t*8+i], 105 MB
__device__ float4 g_part[(size_t)BATCH * PNUM * 4];           // per-quarter argmax partials
__device__ __half g_Ah[(size_t)MDIM * DDIM];                  // 16 MB
__device__ __half g_Al[(size_t)MDIM * DDIM];                  // 16 MB
__device__ __half g_Bh[(size_t)NPAD * DDIM];                  // 1.6 MB
__device__ __half g_Bl[(size_t)NPAD * DDIM];                  // 1.6 MB

// ---------------------------------------------------------------------------
// Kernel 1: normalize x rows, fp16 2-way split (x2048) -> g_Ah, g_Al
// ---------------------------------------------------------------------------
__global__ void split_x_kernel(const float* __restrict__ x) {
    int m = blockIdx.x;
    int t = threadIdx.x;           // 128 threads, 4 elems each
    const float4* row = (const float4*)(x + (size_t)m * DDIM);
    float4 v = row[t];
    float s = v.x*v.x + v.y*v.y + v.z*v.z + v.w*v.w;
    #pragma unroll
    for (int o = 16; o; o >>= 1) s += __shfl_down_sync(0xffffffffu, s, o);
    __shared__ float ws[4];
    __shared__ float sinv;
    if ((t & 31) == 0) ws[t >> 5] = s;
    __syncthreads();
    if (t == 0) sinv = 1.0f / fmaxf(sqrtf(ws[0] + ws[1] + ws[2] + ws[3]), 1e-12f);
    __syncthreads();
    float inv = sinv * SCALE;
    float xv[4] = {v.x * inv, v.y * inv, v.z * inv, v.w * inv};
    __half h[4], l[4];
    #pragma unroll
    for (int j = 0; j < 4; j++) {
        h[j] = __float2half(xv[j]);
        float r = xv[j] - __half2float(h[j]);
        l[j] = __float2half(r);
    }
    size_t off = (size_t)m * DDIM + 4 * t;
    *(__half2*)(g_Ah + off)     = __half2(h[0], h[1]);
    *(__half2*)(g_Ah + off + 2) = __half2(h[2], h[3]);
    *(__half2*)(g_Al + off)     = __half2(l[0], l[1]);
    *(__half2*)(g_Al + off + 2) = __half2(l[2], l[3]);
}

// ---------------------------------------------------------------------------
// Kernel 2: normalize prototypes, fp16 split (x2048) -> g_Bh, g_Bl [n][512].
// Pad rows (n >= 1600) zeroed.
// ---------------------------------------------------------------------------
__global__ void split_proto_kernel(const float* __restrict__ proto) {
    int p = blockIdx.x;
    int tid = (int)threadIdx.x;
    if (p >= PNUM) {   // zero pad rows
        size_t base = (size_t)p * NPS * DDIM;
        __half2 z(__half(0.f), __half(0.f));
        for (int idx = tid; idx < NPS * DDIM / 2; idx += 256) {
            ((__half2*)(g_Bh + base))[idx] = z;
            ((__half2*)(g_Bl + base))[idx] = z;
        }
        return;
    }
    __shared__ float sp[DDIM * NPS];   // 16 KB
    __shared__ float sinv[NPS];
    const float* base = proto + (size_t)p * DDIM * NPS;
    for (int idx = tid; idx < DDIM * NPS; idx += 256) sp[idx] = base[idx];
    __syncthreads();
    int w = tid >> 5, lane = tid & 31;
    if (w < NPS) {
        float s = 0.0f;
        for (int d = lane; d < DDIM; d += 32) { float v = sp[d*NPS + w]; s += v*v; }
        #pragma unroll
        for (int o = 16; o; o >>= 1) s += __shfl_down_sync(0xffffffffu, s, o);
        if (lane == 0) sinv[w] = 1.0f / fmaxf(sqrtf(s), 1e-12f);
    }
    __syncthreads();
    for (int idx = tid; idx < NPS * DDIM; idx += 256) {
        int i = idx >> 9, d = idx & (DDIM - 1);
        float v = sp[d * NPS + i] * sinv[i] * SCALE;
        __half h = __float2half(v);
        float r = v - __half2float(h);
        __half l = __float2half(r);
        size_t off = (size_t)(p * NPS + i) * DDIM + d;
        g_Bh[off] = h;
        g_Bl[off] = l;
    }
}

// ---------------------------------------------------------------------------
// Kernel 3: fp16 GEMM via mma.sync, register-fragment reuse, 3 combos
// (hh, hl, lh). Epilogue also emits per-(b,p) per-m-quarter argmax partials
// (raw + quantized fl(v+NEG)), with the (i<<9)|t lexicographic tie key.
// ---------------------------------------------------------------------------
#define BM 128
#define BN 128
#define BK 64
#define KITERS (DDIM / BK)            // 8
#define BUF_BYTES (BM * BK * 2)       // 16384 per buffer
#define NSTAGE 3
#define GEMM_SMEM (NSTAGE * 4 * BUF_BYTES)  // 196608

__device__ __forceinline__ uint32_t smem_to_u32(const void* p) {
    uint32_t a;
    asm("{ .reg .u64 t; cvta.to.shared.u64 t, %1; cvt.u32.u64 %0, t; }"
        : "=r"(a) : "l"(p));
    return a;
}
#define CP_ASYNC16(saddr, gptr) \
    asm volatile("cp.async.cg.shared.global [%0], [%1], 16;" \
        :: "r"((uint32_t)(saddr)), "l"(gptr))
#define CP_COMMIT() asm volatile("cp.async.commit_group;" ::: "memory")
#define CP_WAIT(n)  asm volatile("cp.async.wait_group %0;" :: "n"(n) : "memory")

__device__ __forceinline__ void ldsm_x4(uint32_t (&r)[4], uint32_t addr) {
    asm volatile("ldmatrix.sync.aligned.m8n8.x4.shared.b16 {%0,%1,%2,%3}, [%4];"
        : "=r"(r[0]), "=r"(r[1]), "=r"(r[2]), "=r"(r[3]) : "r"(addr));
}
__device__ __forceinline__ void mma16816(float (&d)[4], const uint32_t (&a)[4],
                                         uint32_t b0, uint32_t b1) {
    asm volatile(
        "mma.sync.aligned.m16n8k16.row.col.f32.f16.f16.f32 "
        "{%0,%1,%2,%3}, {%4,%5,%6,%7}, {%8,%9}, {%0,%1,%2,%3};"
        : "+f"(d[0]), "+f"(d[1]), "+f"(d[2]), "+f"(d[3])
        : "r"(a[0]), "r"(a[1]), "r"(a[2]), "r"(a[3]), "r"(b0), "r"(b1));
}
__device__ __forceinline__ void amax_upd(float& bv, int& bk, float v, int k) {
    if (v > bv || (v == bv && k < bk)) { bv = v; bk = k; }
}

__global__ void __launch_bounds__(256)
gemm_mma_kernel(const float* __restrict__ tmask) {
    extern __shared__ __align__(128) char smem[];
    uint32_t sb = smem_to_u32(smem);

    int tid = (int)threadIdx.x;
    int wid = tid >> 5, lane = tid & 31;
    int bm = blockIdx.y * BM, bn = blockIdx.x * BN;
    int wm = (wid >> 2) * 64;
    int wn = (wid & 3) * 32;

    auto buf = [&](int s, int w) -> uint32_t {
        return sb + (uint32_t)(s * 4 + w) * BUF_BYTES;
    };

    const __half* gsrc[4] = {g_Ah + (size_t)bm * DDIM, g_Al + (size_t)bm * DDIM,
                             g_Bh + (size_t)bn * DDIM, g_Bl + (size_t)bn * DDIM};

    auto load_stage = [&](int kc, int s) {
        #pragma unroll
        for (int w = 0; w < 4; w++) {
            const __half* g = gsrc[w] + kc * BK;
            uint32_t sbase = buf(s, w);
            #pragma unroll
            for (int q = 0; q < 4; q++) {
                int idx = tid + q * 256;
                int row = idx >> 3, ch = idx & 7;
                uint32_t so = row * 128 + (uint32_t)((ch ^ (row & 7)) << 4);
                CP_ASYNC16(sbase + so, g + (size_t)row * DDIM + ch * 8);
            }
        }
    };

    float d[4][4][4];
    #pragma unroll
    for (int i = 0; i < 4; i++)
        #pragma unroll
        for (int j = 0; j < 4; j++)
            #pragma unroll
            for (int q = 0; q < 4; q++) d[i][j][q] = 0.0f;

    load_stage(0, 0); CP_COMMIT();
    load_stage(1, 1); CP_COMMIT();
    load_stage(2, 2); CP_COMMIT();

    int s = 0;
    for (int kc = 0; kc < KITERS; kc++) {
        CP_WAIT(2);
        __syncthreads();
        uint32_t aHb = buf(s, 0), aLb = buf(s, 1), bHb = buf(s, 2), bLb = buf(s, 3);
        #pragma unroll
        for (int ks = 0; ks < 4; ks++) {
            uint32_t ah[4][4], al[4][4];
            #pragma unroll
            for (int fm = 0; fm < 4; fm++) {
                int r = wm + fm * 16 + (lane & 15);
                int c = ks * 2 + (lane >> 4);
                uint32_t so = r * 128 + (uint32_t)((c ^ (r & 7)) << 4);
                ldsm_x4(ah[fm], aHb + so);
                ldsm_x4(al[fm], aLb + so);
            }
            uint32_t bh[2][4], bl[2][4];
            #pragma unroll
            for (int g = 0; g < 2; g++) {
                int r = wn + g * 16 + (lane & 7) + ((lane >> 4) << 3);
                int c = ks * 2 + ((lane >> 3) & 1);
                uint32_t so = r * 128 + (uint32_t)((c ^ (r & 7)) << 4);
                ldsm_x4(bh[g], bHb + so);
                ldsm_x4(bl[g], bLb + so);
            }
            #pragma unroll
            for (int fm = 0; fm < 4; fm++)
                #pragma unroll
                for (int fn = 0; fn < 4; fn++) {
                    uint32_t bh0 = bh[fn >> 1][(fn & 1) * 2];
                    uint32_t bh1 = bh[fn >> 1][(fn & 1) * 2 + 1];
                    uint32_t bl0 = bl[fn >> 1][(fn & 1) * 2];
                    uint32_t bl1 = bl[fn >> 1][(fn & 1) * 2 + 1];
                    mma16816(d[fm][fn], ah[fm], bh0, bh1);   // hh
                    mma16816(d[fm][fn], ah[fm], bl0, bl1);   // hl
                    mma16816(d[fm][fn], al[fm], bh0, bh1);   // lh
                }
        }
        __syncthreads();
        if (kc + NSTAGE < KITERS) load_stage(kc + NSTAGE, s);
        CP_COMMIT();   // empty groups at the tail keep wait-depth constant
        s = (s == NSTAGE - 1) ? 0 : s + 1;
    }

    // ---- epilogue: store dist + per-fn (=per-p) argmax partials ----
    int gid = lane >> 2, tig = lane & 3;
    float pv[4], pqv[4]; int pk[4], pqk[4];
    #pragma unroll
    for (int fn = 0; fn < 4; fn++) {
        pv[fn] = -INFINITY; pqv[fn] = -INFINITY;
        pk[fn] = 0x7fffffff; pqk[fn] = 0x7fffffff;
    }

    #pragma unroll
    for (int fm = 0; fm < 4; fm++) {
        int m0 = bm + wm + fm * 16 + gid;
        int m1 = m0 + 8;
        int b = m0 >> 9;              // same for m0, m1
        int t0 = m0 & (TLEN - 1), t1 = m1 & (TLEN - 1);
        float tm0 = tmask[m0], tm1 = tmask[m1];
        float s0 = INVSC * tm0, s1 = INVSC * tm1;
        float na0 = (1.0f - tm0) * NEGC, na1 = (1.0f - tm1) * NEGC;
        #pragma unroll
        for (int fn = 0; fn < 4; fn++) {
            int n = bn + wn + fn * 8 + tig * 2;
            if (n >= NDIM) continue;
            int p = n >> 3, i = n & 7;
            size_t base = ((size_t)(b * PNUM + p) << 12);
            float2 o0, o1;
            o0.x = d[fm][fn][0] * s0 + na0;
            o0.y = d[fm][fn][1] * s0 + na0;
            o1.x = d[fm][fn][2] * s1 + na1;
            o1.y = d[fm][fn][3] * s1 + na1;
            *(float2*)(g_dist + base + (t0 << 3) + i) = o0;
            *(float2*)(g_dist + base + (t1 << 3) + i) = o1;
            int k00 = (i << 9) | t0, k01 = ((i + 1) << 9) | t0;
            int k10 = (i << 9) | t1, k11 = ((i + 1) << 9) | t1;
            amax_upd(pv[fn], pk[fn], o0.x, k00);
            amax_upd(pv[fn], pk[fn], o0.y, k01);
            amax_upd(pv[fn], pk[fn], o1.x, k10);
            amax_upd(pv[fn], pk[fn], o1.y, k11);
            amax_upd(pqv[fn], pqk[fn], o0.x + NEGC, k00);
            amax_upd(pqv[fn], pqk[fn], o0.y + NEGC, k01);
            amax_upd(pqv[fn], pqk[fn], o1.x + NEGC, k10);
            amax_upd(pqv[fn], pqk[fn], o1.y + NEGC, k11);
        }
    }

    float4* sm_part = (float4*)smem;   // 32 entries, reuses stage-0 buffer
    #pragma unroll
    for (int fn = 0; fn < 4; fn++) {
        float v = pv[fn], qv = pqv[fn];
        int k = pk[fn], qk = pqk[fn];
        #pragma unroll
        for (int o = 16; o; o >>= 1) {
            float ov = __shfl_xor_sync(0xffffffffu, v, o);
            int   ok = __shfl_xor_sync(0xffffffffu, k, o);
            amax_upd(v, k, ov, ok);
            float oqv = __shfl_xor_sync(0xffffffffu, qv, o);
            int   oqk = __shfl_xor_sync(0xffffffffu, qk, o);
            amax_upd(qv, qk, oqv, oqk);
        }
        if (lane == 0)
            sm_part[wid * 4 + fn] =
                make_float4(v, __int_as_float(k), qv, __int_as_float(qk));
    }
    __syncthreads();
    if (tid < 16) {
        int wn_i = tid >> 2, fn = tid & 3;
        float4 a = sm_part[wn_i * 4 + fn];          // warp row 0
        float4 c = sm_part[(4 + wn_i) * 4 + fn];    // warp row 1
        float v = a.x; int k = __float_as_int(a.y);
        float qv = a.z; int qk = __float_as_int(a.w);
        amax_upd(v, k, c.x, __float_as_int(c.y));
        amax_upd(qv, qk, c.z, __float_as_int(c.w));
        int n0 = bn + wn_i * 32 + fn * 8;
        int p = n0 >> 3;
        if (p < PNUM) {
            int b = bm >> 9;
            int quarter = (bm >> 7) & 3;
            g_part[(size_t)(b * PNUM + p) * 4 + quarter] =
                make_float4(v, __int_as_float(k), qv, __int_as_float(qk));
        }
    }
}

// ---------------------------------------------------------------------------
// Kernel 4: selection — one warp per (b,p). Combine 4 partials for it-0
// (raw) + fallback (quantized), then 7 windowed iterations reading <=56
// values each straight from g_dist. Same semantics as the proven R8 select.
// ---------------------------------------------------------------------------
__global__ void __launch_bounds__(256)
select_kernel(const float* __restrict__ ps, float* __restrict__ out) {
    int tid = (int)threadIdx.x;
    int wid = tid >> 5, lane = tid & 31;
    int bp = blockIdx.x * 8 + wid;
    int p = bp % PNUM;
    const float* gd = g_dist + ((size_t)bp << 12);

    float fv = -INFINITY, fqv = -INFINITY;
    int fk = 0x7fffffff, fqk = 0x7fffffff;
    if (lane < 4) {
        float4 pr = g_part[(size_t)bp * 4 + lane];
        fv = pr.x; fk = __float_as_int(pr.y);
        fqv = pr.z; fqk = __float_as_int(pr.w);
    }
    #pragma unroll
    for (int o = 2; o; o >>= 1) {
        float ov = __shfl_xor_sync(0xffffffffu, fv, o);
        int   ok = __shfl_xor_sync(0xffffffffu, fk, o);
        amax_upd(fv, fk, ov, ok);
        float oqv = __shfl_xor_sync(0xffffffffu, fqv, o);
        int   oqk = __shfl_xor_sync(0xffffffffu, fqk, o);
        amax_upd(fqv, fqk, oqv, oqk);
    }
    // broadcast lane-0 winner (lanes 4..31 had -INF)
    fv  = __shfl_sync(0xffffffffu, fv, 0);
    fk  = __shfl_sync(0xffffffffu, fk, 0);
    fqv = __shfl_sync(0xffffffffu, fqv, 0);
    fqk = __shfl_sync(0xffffffffu, fqk, 0);

    float rv[NPS]; int re[NPS], rs[NPS];
    rv[0] = fv; re[0] = fk & (TLEN - 1); rs[0] = fk >> 9;
    int msub = 0xFF & ~(1 << rs[0]);
    int pe = re[0];

    #pragma unroll
    for (int it = 1; it < NPS; it++) {
        int wlo = (it == 1) ? max(pe - 3, 0) : (pe + 1);
        int whi = min(pe + 3, TLEN - 1);
        int cnt = (whi >= wlo) ? (whi - wlo + 1) * NPS : 0;
        float bv = -INFINITY;
        int   bk = 0x7fffffff;
        #pragma unroll
        for (int qq = 0; qq < 2; qq++) {
            int q = lane + qq * 32;
            if (q < cnt) {
                int t = wlo + (q >> 3), i = q & 7;
                bool ok2 = (msub >> i) & 1;
                #pragma unroll
                for (int j = 0; j < NPS - 1; j++)
                    if (j < it && re[j] == t) ok2 = false;
                if (ok2) {
                    float v = gd[(t << 3) + i];
                    amax_upd(bv, bk, v, (i << 9) | t);
                }
            }
        }
        #pragma unroll
        for (int o = 16; o; o >>= 1) {
            float ov = __shfl_xor_sync(0xffffffffu, bv, o);
            int   ok = __shfl_xor_sync(0xffffffffu, bk, o);
            amax_upd(bv, bk, ov, ok);
        }
        float recv;
        if (bk == 0x7fffffff) { bk = fqk; recv = fqv; }
        else                  recv = bv;
        int tt = bk & (TLEN - 1), ii = bk >> 9;
        rv[it] = recv; re[it] = tt; rs[it] = ii;
        msub &= ~(1 << ii);
        pe = tt;
    }

    if (lane == 0) {
        int ord[NPS];
        #pragma unroll
        for (int j = 0; j < NPS; j++) ord[j] = j;
        for (int a = 1; a < NPS; a++) {
            int o = ord[a], key = rs[o], bb = a - 1;
            while (bb >= 0 && rs[ord[bb]] > key) { ord[bb + 1] = ord[bb]; bb--; }
            ord[bb + 1] = o;
        }
        const float* pp = ps + (size_t)p * NPS;
        float slots[NPS];
        float factor = 0.0f;
        #pragma unroll
        for (int j = 0; j < NPS; j++) {
            float s = 1.0f / (1.0f + expf(-pp[j]));
            slots[j] = s; factor += s;
        }
        factor += 1e-10f;
        float acc = 0.0f;
        #pragma unroll
        for (int j = 0; j < NPS; j++)
            acc += rv[ord[j]] * (slots[j] * (float)NPS / factor);
        out[bp] = acc;
        out[BATCH * PNUM + bp] = (float)NPS - acc;
        #pragma unroll
        for (int j = 0; j < NPS; j++)
            out[2 * BATCH * PNUM + bp * NPS + j] = (float)re[ord[j]];
    }
}

// ---------------------------------------------------------------------------
extern "C" void kernel_launch(void* const* d_in, const int* in_sizes, int n_in,
                              void* d_out, int out_size) {
    (void)in_sizes; (void)n_in; (void)out_size;
    const float* x     = (const float*)d_in[0];
    const float* tmask = (const float*)d_in[1];
    const float* proto = (const float*)d_in[2];
    const float* psel  = (const float*)d_in[3];
    float* out = (float*)d_out;

    cudaFuncSetAttribute(gemm_mma_kernel,
                         cudaFuncAttributeMaxDynamicSharedMemorySize, GEMM_SMEM);

    split_x_kernel<<<MDIM, 128>>>(x);
    split_proto_kernel<<<NPAD / NPS, 256>>>(proto);
    gemm_mma_kernel<<<dim3(NPAD / BN, MDIM / BM), 256, GEMM_SMEM>>>(tmask);
    select_kernel<<<BATCH * PNUM / 8, 256>>>(psel, out);
}